// round 2
// baseline (speedup 1.0000x reference)
#include <cuda_runtime.h>

#define B_   2
#define S_   2048
#define D_   1024
#define H_   16
#define HD_  64
#define M_   (B_*S_)     // 4096
#define G_   (B_*H_)     // 32

// ---- scratch (static device arrays; no allocation allowed) ----
__device__ float g_q [(size_t)G_*S_*HD_];   // [b,h,s,hd]
__device__ float g_k [(size_t)G_*S_*HD_];
__device__ float g_v [(size_t)G_*S_*HD_];
__device__ float g_vt[(size_t)G_*HD_*S_];   // V transposed: [g, d, j]
__device__ float g_p [(size_t)G_*S_*S_];    // attention scores/probs (512 MB)
__device__ float g_oh[(size_t)G_*S_*HD_];   // attn output, head layout
__device__ float g_ob[(size_t)M_*D_];       // after exclusion, [b,s,d] layout

// ============================================================================
// Generic tiled GEMM:  C[m,n] = scale * sum_k A[m,k]*W[n,k]  (+ bias[n])
// A: row-major [M, lda], W: row-major [N, ldw]  (both K-contiguous)
// MODE 0: flat store C[m*ldc + n]
// MODE 1: projection store to [b,h,s,hd] head layout (C = q/k/v buffer)
// Batched via blockIdx.z with strides sA/sW/sC.
// All dims divide tile sizes exactly for every use here (no bounds checks).
// ============================================================================
template<int BM, int BN, int BK, int MODE>
__global__ void __launch_bounds__(256, 2)
gemm_abt(const float* __restrict__ A, const float* __restrict__ W,
         const float* __restrict__ bias, float* __restrict__ C,
         int K, int lda, int ldw, int ldc,
         long sA, long sW, long sC, float scale)
{
    constexpr int RM = BM / 64;          // row fragments of 4
    constexpr int RN = BN / 64;          // col fragments of 4
    constexpr int C4 = BK / 4;           // float4s per k-tile row
    constexpr int ALD = (BM * C4) / 256; // A float4 loads per thread
    constexpr int WLD = (BN * C4) / 256;

    __shared__ float As[BK][BM];
    __shared__ float Ws[BK][BN];

    const int g = blockIdx.z;
    A += (long)g * sA;
    W += (long)g * sW;
    C += (long)g * sC;

    const int m0  = blockIdx.y * BM;
    const int n0  = blockIdx.x * BN;
    const int tid = threadIdx.x;
    const int tx  = tid & 15;
    const int ty  = tid >> 4;

    float acc[RM][RN][16];
    #pragma unroll
    for (int a = 0; a < RM; ++a)
        #pragma unroll
        for (int b = 0; b < RN; ++b)
            #pragma unroll
            for (int c = 0; c < 16; ++c) acc[a][b][c] = 0.0f;

    for (int k0 = 0; k0 < K; k0 += BK) {
        // load A tile, store transposed (k-major) into shared
        #pragma unroll
        for (int l = 0; l < ALD; ++l) {
            int idx = tid + l * 256;
            int row = idx / C4;
            int c4  = idx - row * C4;
            float4 val = *(const float4*)(A + (long)(m0 + row) * lda + k0 + c4 * 4);
            As[c4*4+0][row] = val.x;
            As[c4*4+1][row] = val.y;
            As[c4*4+2][row] = val.z;
            As[c4*4+3][row] = val.w;
        }
        // load W tile transposed
        #pragma unroll
        for (int l = 0; l < WLD; ++l) {
            int idx = tid + l * 256;
            int row = idx / C4;
            int c4  = idx - row * C4;
            float4 val = *(const float4*)(W + (long)(n0 + row) * ldw + k0 + c4 * 4);
            Ws[c4*4+0][row] = val.x;
            Ws[c4*4+1][row] = val.y;
            Ws[c4*4+2][row] = val.z;
            Ws[c4*4+3][row] = val.w;
        }
        __syncthreads();

        #pragma unroll
        for (int k = 0; k < BK; ++k) {
            float4 af4[RM], bf4[RN];
            #pragma unroll
            for (int rm = 0; rm < RM; ++rm)
                af4[rm] = *(const float4*)&As[k][rm*64 + ty*4];
            #pragma unroll
            for (int rn = 0; rn < RN; ++rn)
                bf4[rn] = *(const float4*)&Ws[k][rn*64 + tx*4];
            #pragma unroll
            for (int rm = 0; rm < RM; ++rm) {
                const float* ap = (const float*)&af4[rm];
                #pragma unroll
                for (int rn = 0; rn < RN; ++rn) {
                    const float* bp = (const float*)&bf4[rn];
                    #pragma unroll
                    for (int i = 0; i < 4; ++i)
                        #pragma unroll
                        for (int j = 0; j < 4; ++j)
                            acc[rm][rn][i*4+j] += ap[i] * bp[j];
                }
            }
        }
        __syncthreads();
    }

    // epilogue
    #pragma unroll
    for (int rm = 0; rm < RM; ++rm) {
        #pragma unroll
        for (int i = 0; i < 4; ++i) {
            int m = m0 + rm*64 + ty*4 + i;
            #pragma unroll
            for (int rn = 0; rn < RN; ++rn) {
                int n = n0 + rn*64 + tx*4;
                float4 r;
                r.x = acc[rm][rn][i*4+0] * scale;
                r.y = acc[rm][rn][i*4+1] * scale;
                r.z = acc[rm][rn][i*4+2] * scale;
                r.w = acc[rm][rn][i*4+3] * scale;
                if (bias) {
                    float4 bb = *(const float4*)(bias + n);
                    r.x += bb.x; r.y += bb.y; r.z += bb.z; r.w += bb.w;
                }
                if (MODE == 0) {
                    *(float4*)(C + (long)m * ldc + n) = r;
                } else {
                    // projection: m = b*S + s, n = h*HD + hd -> [b,h,s,hd]
                    int b  = m >> 11;        // / 2048
                    int s  = m & 2047;
                    int h  = n >> 6;
                    int hd = n & 63;
                    *(float4*)(C + (((long)(b*H_ + h) * S_ + s) * HD_ + hd)) = r;
                }
            }
        }
    }
}

// ============================================================================
// V transpose per batch: Vt[g][d][j] = V[g][j][d]
// ============================================================================
__global__ void __launch_bounds__(256)
vtrans(const float* __restrict__ V, float* __restrict__ Vt)
{
    __shared__ float t[32][33];
    int g  = blockIdx.z;
    int j0 = blockIdx.x * 32;
    int d0 = blockIdx.y * 32;
    int x = threadIdx.x, y = threadIdx.y;   // 32 x 8
    const float* Vg  = V  + (long)g * S_ * HD_;
    float*       Vtg = Vt + (long)g * HD_ * S_;
    #pragma unroll
    for (int r = 0; r < 4; ++r)
        t[y + r*8][x] = Vg[(long)(j0 + y + r*8) * HD_ + d0 + x];
    __syncthreads();
    #pragma unroll
    for (int r = 0; r < 4; ++r)
        Vtg[(long)(d0 + y + r*8) * S_ + j0 + x] = t[x][y + r*8];
}

// ============================================================================
// Row softmax over 2048 cols; one block (256 threads) per row
// ============================================================================
__global__ void __launch_bounds__(256)
softmax_rows(float* __restrict__ P)
{
    long row = blockIdx.x;
    float4* p = (float4*)(P + row * (long)S_);
    int tid = threadIdx.x;

    float4 a = p[tid];
    float4 b = p[tid + 256];

    float mx = fmaxf(fmaxf(fmaxf(a.x, a.y), fmaxf(a.z, a.w)),
                     fmaxf(fmaxf(b.x, b.y), fmaxf(b.z, b.w)));
    __shared__ float red[8];
    #pragma unroll
    for (int o = 16; o > 0; o >>= 1)
        mx = fmaxf(mx, __shfl_xor_sync(0xffffffffu, mx, o));
    if ((tid & 31) == 0) red[tid >> 5] = mx;
    __syncthreads();
    mx = red[0];
    #pragma unroll
    for (int i = 1; i < 8; ++i) mx = fmaxf(mx, red[i]);
    __syncthreads();

    a.x = __expf(a.x - mx); a.y = __expf(a.y - mx);
    a.z = __expf(a.z - mx); a.w = __expf(a.w - mx);
    b.x = __expf(b.x - mx); b.y = __expf(b.y - mx);
    b.z = __expf(b.z - mx); b.w = __expf(b.w - mx);

    float sm = a.x + a.y + a.z + a.w + b.x + b.y + b.z + b.w;
    #pragma unroll
    for (int o = 16; o > 0; o >>= 1)
        sm += __shfl_xor_sync(0xffffffffu, sm, o);
    if ((tid & 31) == 0) red[tid >> 5] = sm;
    __syncthreads();
    sm = 0.0f;
    #pragma unroll
    for (int i = 0; i < 8; ++i) sm += red[i];

    float inv = 1.0f / sm;
    a.x *= inv; a.y *= inv; a.z *= inv; a.w *= inv;
    b.x *= inv; b.y *= inv; b.z *= inv; b.w *= inv;
    p[tid] = a;
    p[tid + 256] = b;
}

// ============================================================================
// Gram-Schmidt exclusion + relayout to [b,s,d]; one warp per (g,s) row of 64
// ============================================================================
__global__ void __launch_bounds__(256)
exclude_gs(const float* __restrict__ OH, const float* __restrict__ V,
           float* __restrict__ OB)
{
    int gw   = (blockIdx.x * 256 + threadIdx.x) >> 5;  // 0 .. G_*S_-1
    int lane = threadIdx.x & 31;
    int g = gw >> 11;       // / 2048
    int s = gw & 2047;
    long base = ((long)g * S_ + s) * HD_;

    float2 o = *(const float2*)(OH + base + lane*2);
    float2 v = *(const float2*)(V  + base + lane*2);
    float dov = o.x*v.x + o.y*v.y;
    float dvv = v.x*v.x + v.y*v.y;
    #pragma unroll
    for (int off = 16; off > 0; off >>= 1) {
        dov += __shfl_xor_sync(0xffffffffu, dov, off);
        dvv += __shfl_xor_sync(0xffffffffu, dvv, off);
    }
    float al = dov / (dvv + 1e-8f);
    o.x -= al * v.x;
    o.y -= al * v.y;

    int b = g >> 4, h = g & 15;
    *(float2*)(OB + ((long)(b * S_ + s) * D_ + h * HD_ + lane*2)) = o;
}

// ============================================================================
extern "C" void kernel_launch(void* const* d_in, const int* in_sizes, int n_in,
                              void* d_out, int out_size)
{
    const float* x  = (const float*)d_in[0];
    const float* wq = (const float*)d_in[1];
    const float* bq = (const float*)d_in[2];
    const float* wk = (const float*)d_in[3];
    const float* bk = (const float*)d_in[4];
    const float* wv = (const float*)d_in[5];
    const float* bv = (const float*)d_in[6];
    const float* wo = (const float*)d_in[7];
    const float* bo = (const float*)d_in[8];
    float* out = (float*)d_out;

    float *q, *k, *v, *vt, *p, *oh, *ob;
    cudaGetSymbolAddress((void**)&q,  g_q);
    cudaGetSymbolAddress((void**)&k,  g_k);
    cudaGetSymbolAddress((void**)&v,  g_v);
    cudaGetSymbolAddress((void**)&vt, g_vt);
    cudaGetSymbolAddress((void**)&p,  g_p);
    cudaGetSymbolAddress((void**)&oh, g_oh);
    cudaGetSymbolAddress((void**)&ob, g_ob);

    // 1) Q/K/V projections: [4096,1024] x [1024,1024]^T -> head layout
    dim3 gproj(D_/128, M_/128, 1);
    gemm_abt<128,128,16,1><<<gproj, 256>>>(x, wq, bq, q, D_, D_, D_, 0, 0, 0, 0, 1.0f);
    gemm_abt<128,128,16,1><<<gproj, 256>>>(x, wk, bk, k, D_, D_, D_, 0, 0, 0, 0, 1.0f);
    gemm_abt<128,128,16,1><<<gproj, 256>>>(x, wv, bv, v, D_, D_, D_, 0, 0, 0, 0, 1.0f);

    // 2) transpose V for the PV GEMM
    vtrans<<<dim3(S_/32, HD_/32, G_), dim3(32, 8)>>>(v, vt);

    // 3) scores = Q K^T / 8  (batched over 32 heads)
    gemm_abt<128,128,16,0><<<dim3(S_/128, S_/128, G_), 256>>>(
        q, k, nullptr, p, HD_, HD_, HD_, S_,
        (long)S_*HD_, (long)S_*HD_, (long)S_*S_, 0.125f);

    // 4) softmax rows
    softmax_rows<<<G_*S_, 256>>>(p);

    // 5) O = P V  (batched, N=64)
    gemm_abt<128,64,16,0><<<dim3(1, S_/128, G_), 256>>>(
        p, vt, nullptr, oh, S_, S_, S_, HD_,
        (long)S_*S_, (long)HD_*S_, (long)S_*HD_, 1.0f);

    // 6) Gram-Schmidt exclusion + relayout to [b,s,d]
    exclude_gs<<<(G_*S_)/8, 256>>>(oh, v, ob);

    // 7) output projection -> d_out
    gemm_abt<128,128,16,0><<<dim3(D_/128, M_/128, 1), 256>>>(
        ob, wo, bo, out, D_, D_, D_, D_, 0, 0, 0, 1.0f);
}

// round 5
// speedup vs baseline: 1.7662x; 1.7662x over previous
#include <cuda_runtime.h>
#include <cuda_bf16.h>
#include <cstdint>

#define B_   2
#define S_   2048
#define D_   1024
#define H_   16
#define HD_  64
#define M_   (B_*S_)     // 4096
#define G_   (B_*H_)     // 32

// ---- scratch (static device arrays; no allocation allowed) ----
__device__ float g_q [(size_t)G_*S_*HD_];   // [b,h,s,hd]
__device__ float g_k [(size_t)G_*S_*HD_];
__device__ float g_v [(size_t)G_*S_*HD_];
__device__ float g_vt[(size_t)G_*HD_*S_];   // V transposed: [g, d, j]
__device__ float g_p [(size_t)G_*S_*S_];    // attention scores (512 MB)
__device__ float g_oh[(size_t)G_*S_*HD_];   // attn output, head layout
__device__ float g_ob[(size_t)M_*D_];       // after exclusion, [b,s,d]
__device__ float g_mx[(size_t)G_*S_];       // softmax row max
__device__ float g_iv[(size_t)G_*S_];       // softmax row 1/sum

// ============================================================================
// MMA / ldmatrix helpers (baseline PTX, compiles for sm_103)
// ============================================================================
__device__ __forceinline__ uint32_t smem_u32(const void* p) {
    uint32_t a;
    asm("{ .reg .u64 t; cvta.to.shared.u64 t, %1; cvt.u32.u64 %0, t; }"
        : "=r"(a) : "l"(p));
    return a;
}

__device__ __forceinline__ void ldm_x4(uint32_t* r, uint32_t addr) {
    asm volatile("ldmatrix.sync.aligned.m8n8.x4.shared.b16 {%0,%1,%2,%3}, [%4];"
        : "=r"(r[0]), "=r"(r[1]), "=r"(r[2]), "=r"(r[3]) : "r"(addr));
}

__device__ __forceinline__ void mma16816(float* c, const uint32_t* a,
                                         uint32_t b0, uint32_t b1) {
    asm volatile(
        "mma.sync.aligned.m16n8k16.row.col.f32.bf16.bf16.f32 "
        "{%0,%1,%2,%3}, {%4,%5,%6,%7}, {%8,%9}, {%0,%1,%2,%3};"
        : "+f"(c[0]), "+f"(c[1]), "+f"(c[2]), "+f"(c[3])
        : "r"(a[0]), "r"(a[1]), "r"(a[2]), "r"(a[3]), "r"(b0), "r"(b1));
}

__device__ __forceinline__ uint32_t packbf(__nv_bfloat16 x, __nv_bfloat16 y) {
    __nv_bfloat162 t; t.x = x; t.y = y;
    return *(uint32_t*)&t;
}

// ============================================================================
// Staging: fp32 gmem (K-contiguous rows) -> hi/lo bf16 swizzled smem tiles.
// Tile = rows x 32 k-elems; smem row = 64 B (32 bf16); chunk = 16 B (8 elems).
// Swizzle: phys_chunk = chunk ^ ((row>>1)&3)  -> conflict-free STS.128 and
// conflict-free 8-row ldmatrix reads.
// ============================================================================
template<int ITEMS>
__device__ __forceinline__ void stage_load(float4 (*pf)[2],
    const float* __restrict__ src, int lds, int kc, int tid)
{
    #pragma unroll
    for (int i = 0; i < ITEMS; ++i) {
        int idx = tid + i * 256;
        int row = idx >> 2, ci = idx & 3;
        const float* p = src + (long)row * lds + kc + ci * 8;
        pf[i][0] = *(const float4*)p;
        pf[i][1] = *(const float4*)(p + 4);
    }
}

template<int ITEMS, bool SM>
__device__ __forceinline__ void stage_store(float4 (*pf)[2], char* hi, char* lo,
    const float* __restrict__ rmx, const float* __restrict__ riv, int tid)
{
    #pragma unroll
    for (int i = 0; i < ITEMS; ++i) {
        int idx = tid + i * 256;
        int row = idx >> 2, ci = idx & 3;
        float f[8] = { pf[i][0].x, pf[i][0].y, pf[i][0].z, pf[i][0].w,
                       pf[i][1].x, pf[i][1].y, pf[i][1].z, pf[i][1].w };
        if (SM) {
            float m = rmx[row], v = riv[row];
            #pragma unroll
            for (int j = 0; j < 8; ++j) f[j] = __expf(f[j] - m) * v;
        }
        uint32_t hw[4], lw[4];
        #pragma unroll
        for (int j = 0; j < 4; ++j) {
            __nv_bfloat16 h0 = __float2bfloat16_rn(f[2*j]);
            __nv_bfloat16 h1 = __float2bfloat16_rn(f[2*j+1]);
            hw[j] = packbf(h0, h1);
            lw[j] = packbf(__float2bfloat16_rn(f[2*j]   - __bfloat162float(h0)),
                           __float2bfloat16_rn(f[2*j+1] - __bfloat162float(h1)));
        }
        uint32_t off = (uint32_t)(row * 64) + (uint32_t)(((ci ^ ((row >> 1) & 3)) << 4));
        *(uint4*)(hi + off) = make_uint4(hw[0], hw[1], hw[2], hw[3]);
        *(uint4*)(lo + off) = make_uint4(lw[0], lw[1], lw[2], lw[3]);
    }
}

// ============================================================================
// HMMA GEMM: C[m,n] = scale * sum_k A[m,k]*W[n,k] (+bias[n])
// BM=128, BK=32, BN template (128 or 64). bf16 2-term split (3 MMAs/product).
// Double-buffered smem, register prefetch of next chunk.
// MODE 0: flat store. MODE 1: [b,h,s,hd] head store. SM: softmax-normalize A.
// ============================================================================
template<int BN, int MODE, bool SM>
__global__ void __launch_bounds__(256, 1)
gemm_mma(const float* __restrict__ A, const float* __restrict__ W,
         const float* __restrict__ bias, float* __restrict__ C,
         const float* __restrict__ rmx, const float* __restrict__ riv,
         int K, int lda, int ldw, int ldc,
         long sA, long sW, long sC, float scale)
{
    extern __shared__ char smem[];
    constexpr int WGN    = (BN == 128) ? 4 : 2;     // warps along n
    constexpr int WTM    = (BN == 128) ? 64 : 32;   // warp tile m
    constexpr int MT     = WTM / 16;                // m16 tiles per warp
    constexpr int ABYTES = 128 * 64;                // 8 KB per (hi|lo)
    constexpr int BBYTES = BN * 64;
    constexpr int STG    = 2 * ABYTES + 2 * BBYTES;
    constexpr int AITEM  = 2;                       // 128*4/256
    constexpr int BITEM  = (BN * 4) / 256;          // 2 or 1

    const int tid = threadIdx.x;
    const int wid = tid >> 5;
    const int l   = tid & 31;
    const int gz  = blockIdx.z;
    const int m0  = blockIdx.y * 128;
    const int n0  = blockIdx.x * BN;

    const int wm = (wid / WGN) * WTM;
    const int wn = (wid % WGN) * 32;

    const float* At = A + (long)gz * sA + (long)m0 * lda;
    const float* Wt = W + (long)gz * sW + (long)n0 * ldw;
    float*       Ct = C + (long)gz * sC;
    const float* rmx_t = SM ? (rmx + (long)gz * S_ + m0) : nullptr;
    const float* riv_t = SM ? (riv + (long)gz * S_ + m0) : nullptr;

    // lane-level ldmatrix address components
    const int aRow = (l & 15);          // row within 16-row m-tile
    const int aCk  = (l >> 4);          // k half (0/1)
    const int bRow = ((l >> 4) & 1) * 8 + (l & 7);
    const int bCk  = (l >> 3) & 1;

    int raRow[MT], raSwz[MT];
    #pragma unroll
    for (int mt = 0; mt < MT; ++mt) {
        raRow[mt] = wm + mt * 16 + aRow;
        raSwz[mt] = (raRow[mt] >> 1) & 3;
    }
    int rbRow[2], rbSwz[2];
    #pragma unroll
    for (int nb = 0; nb < 2; ++nb) {
        rbRow[nb] = wn + nb * 16 + bRow;
        rbSwz[nb] = (rbRow[nb] >> 1) & 3;
    }

    float acc[MT][4][4];
    #pragma unroll
    for (int a = 0; a < MT; ++a)
        #pragma unroll
        for (int b = 0; b < 4; ++b)
            #pragma unroll
            for (int c = 0; c < 4; ++c) acc[a][b][c] = 0.0f;

    const uint32_t sb = smem_u32(smem);
    const int nch = K / 32;

    float4 pfA[AITEM][2], pfB[BITEM][2];
    stage_load<AITEM>(pfA, At, lda, 0, tid);
    stage_load<BITEM>(pfB, Wt, ldw, 0, tid);

    for (int c = 0; c < nch; ++c) {
        char* buf = smem + (c & 1) * STG;
        stage_store<AITEM, SM>   (pfA, buf,              buf + ABYTES, rmx_t, riv_t, tid);
        stage_store<BITEM, false>(pfB, buf + 2*ABYTES,   buf + 2*ABYTES + BBYTES,
                                  nullptr, nullptr, tid);
        __syncthreads();

        if (c + 1 < nch) {
            stage_load<AITEM>(pfA, At, lda, (c + 1) * 32, tid);
            stage_load<BITEM>(pfB, Wt, ldw, (c + 1) * 32, tid);
        }

        const uint32_t ahi = sb + (c & 1) * STG;
        const uint32_t alo = ahi + ABYTES;
        const uint32_t bhi = alo + ABYTES;
        const uint32_t blo = bhi + BBYTES;

        #pragma unroll
        for (int ks = 0; ks < 2; ++ks) {
            uint32_t ah[MT][4], al[MT][4], bh[2][4], bl[2][4];
            #pragma unroll
            for (int mt = 0; mt < MT; ++mt) {
                uint32_t off = (uint32_t)(raRow[mt] * 64)
                             + (uint32_t)((((2*ks + aCk) ^ raSwz[mt]) << 4));
                ldm_x4(ah[mt], ahi + off);
                ldm_x4(al[mt], alo + off);
            }
            #pragma unroll
            for (int nb = 0; nb < 2; ++nb) {
                uint32_t off = (uint32_t)(rbRow[nb] * 64)
                             + (uint32_t)((((2*ks + bCk) ^ rbSwz[nb]) << 4));
                ldm_x4(bh[nb], bhi + off);
                ldm_x4(bl[nb], blo + off);
            }
            #pragma unroll
            for (int mt = 0; mt < MT; ++mt) {
                #pragma unroll
                for (int nt = 0; nt < 4; ++nt) {
                    const uint32_t* pbh = &bh[nt >> 1][(nt & 1) * 2];
                    const uint32_t* pbl = &bl[nt >> 1][(nt & 1) * 2];
                    mma16816(acc[mt][nt], ah[mt], pbh[0], pbh[1]);
                    mma16816(acc[mt][nt], ah[mt], pbl[0], pbl[1]);
                    mma16816(acc[mt][nt], al[mt], pbh[0], pbh[1]);
                }
            }
        }
        __syncthreads();
    }

    // ---- epilogue ----
    #pragma unroll
    for (int mt = 0; mt < MT; ++mt) {
        #pragma unroll
        for (int nt = 0; nt < 4; ++nt) {
            int n = n0 + wn + nt * 8 + (l & 3) * 2;
            float2 bb = make_float2(0.f, 0.f);
            if (bias) bb = *(const float2*)(bias + n);
            #pragma unroll
            for (int half = 0; half < 2; ++half) {
                int m = m0 + wm + mt * 16 + (l >> 2) + half * 8;
                float2 r;
                r.x = acc[mt][nt][half*2]   * scale + bb.x;
                r.y = acc[mt][nt][half*2+1] * scale + bb.y;
                if (MODE == 0) {
                    *(float2*)(Ct + (long)m * ldc + n) = r;
                } else {
                    int b2 = m >> 11, s = m & 2047;
                    int h = n >> 6, hd = n & 63;
                    *(float2*)(Ct + (((long)(b2 * H_ + h) * S_ + s) * HD_ + hd)) = r;
                }
            }
        }
    }
}

// ============================================================================
// V transpose per batch: Vt[g][d][j] = V[g][j][d]
// ============================================================================
__global__ void __launch_bounds__(256)
vtrans(const float* __restrict__ V, float* __restrict__ Vt)
{
    __shared__ float t[32][33];
    int g  = blockIdx.z;
    int j0 = blockIdx.x * 32;
    int d0 = blockIdx.y * 32;
    int x = threadIdx.x, y = threadIdx.y;   // 32 x 8
    const float* Vg  = V  + (long)g * S_ * HD_;
    float*       Vtg = Vt + (long)g * HD_ * S_;
    #pragma unroll
    for (int r = 0; r < 4; ++r)
        t[y + r*8][x] = Vg[(long)(j0 + y + r*8) * HD_ + d0 + x];
    __syncthreads();
    #pragma unroll
    for (int r = 0; r < 4; ++r)
        Vtg[(long)(d0 + y + r*8) * S_ + j0 + x] = t[x][y + r*8];
}

// ============================================================================
// Row softmax stats: max and 1/sum(exp) per row of 2048 scores
// ============================================================================
__global__ void __launch_bounds__(256)
rowstats(const float* __restrict__ P, float* __restrict__ gmx, float* __restrict__ giv)
{
    long row = blockIdx.x;
    const float4* p = (const float4*)(P + row * (long)S_);
    int tid = threadIdx.x;

    float4 a = p[tid];
    float4 b = p[tid + 256];

    float mx = fmaxf(fmaxf(fmaxf(a.x, a.y), fmaxf(a.z, a.w)),
                     fmaxf(fmaxf(b.x, b.y), fmaxf(b.z, b.w)));
    __shared__ float red[8];
    #pragma unroll
    for (int o = 16; o > 0; o >>= 1)
        mx = fmaxf(mx, __shfl_xor_sync(0xffffffffu, mx, o));
    if ((tid & 31) == 0) red[tid >> 5] = mx;
    __syncthreads();
    mx = red[0];
    #pragma unroll
    for (int i = 1; i < 8; ++i) mx = fmaxf(mx, red[i]);
    __syncthreads();

    float sm = __expf(a.x - mx) + __expf(a.y - mx) + __expf(a.z - mx) + __expf(a.w - mx)
             + __expf(b.x - mx) + __expf(b.y - mx) + __expf(b.z - mx) + __expf(b.w - mx);
    #pragma unroll
    for (int o = 16; o > 0; o >>= 1)
        sm += __shfl_xor_sync(0xffffffffu, sm, o);
    if ((tid & 31) == 0) red[tid >> 5] = sm;
    __syncthreads();
    if (tid == 0) {
        sm = 0.0f;
        #pragma unroll
        for (int i = 0; i < 8; ++i) sm += red[i];
        gmx[row] = mx;
        giv[row] = 1.0f / sm;
    }
}

// ============================================================================
// Gram-Schmidt exclusion + relayout to [b,s,d]; one warp per (g,s)
// ============================================================================
__global__ void __launch_bounds__(256)
exclude_gs(const float* __restrict__ OH, const float* __restrict__ V,
           float* __restrict__ OB)
{
    int gw   = (blockIdx.x * 256 + threadIdx.x) >> 5;
    int lane = threadIdx.x & 31;
    int g = gw >> 11;
    int s = gw & 2047;
    long base = ((long)g * S_ + s) * HD_;

    float2 o = *(const float2*)(OH + base + lane*2);
    float2 v = *(const float2*)(V  + base + lane*2);
    float dov = o.x*v.x + o.y*v.y;
    float dvv = v.x*v.x + v.y*v.y;
    #pragma unroll
    for (int off = 16; off > 0; off >>= 1) {
        dov += __shfl_xor_sync(0xffffffffu, dov, off);
        dvv += __shfl_xor_sync(0xffffffffu, dvv, off);
    }
    float al = dov / (dvv + 1e-8f);
    o.x -= al * v.x;
    o.y -= al * v.y;

    int b = g >> 4, h = g & 15;
    *(float2*)(OB + ((long)(b * S_ + s) * D_ + h * HD_ + lane*2)) = o;
}

// ============================================================================
extern "C" void kernel_launch(void* const* d_in, const int* in_sizes, int n_in,
                              void* d_out, int out_size)
{
    const float* x  = (const float*)d_in[0];
    const float* wq = (const float*)d_in[1];
    const float* bq = (const float*)d_in[2];
    const float* wk = (const float*)d_in[3];
    const float* bk = (const float*)d_in[4];
    const float* wv = (const float*)d_in[5];
    const float* bv = (const float*)d_in[6];
    const float* wo = (const float*)d_in[7];
    const float* bo = (const float*)d_in[8];
    float* out = (float*)d_out;

    float *q, *k, *v, *vt, *p, *oh, *ob, *mx, *iv;
    cudaGetSymbolAddress((void**)&q,  g_q);
    cudaGetSymbolAddress((void**)&k,  g_k);
    cudaGetSymbolAddress((void**)&v,  g_v);
    cudaGetSymbolAddress((void**)&vt, g_vt);
    cudaGetSymbolAddress((void**)&p,  g_p);
    cudaGetSymbolAddress((void**)&oh, g_oh);
    cudaGetSymbolAddress((void**)&ob, g_ob);
    cudaGetSymbolAddress((void**)&mx, g_mx);
    cudaGetSymbolAddress((void**)&iv, g_iv);

    // dynamic smem: 2 stages of (A hi/lo 16KB + B hi/lo BN*128)
    const int SM128 = 2 * (2*128*64 + 2*128*64);   // 65536
    const int SM64  = 2 * (2*128*64 + 2*64*64);    // 49152
    cudaFuncSetAttribute(gemm_mma<128,1,false>, cudaFuncAttributeMaxDynamicSharedMemorySize, SM128);
    cudaFuncSetAttribute(gemm_mma<128,0,false>, cudaFuncAttributeMaxDynamicSharedMemorySize, SM128);
    cudaFuncSetAttribute(gemm_mma<64,0,true>,   cudaFuncAttributeMaxDynamicSharedMemorySize, SM64);

    // 1) Q/K/V projections -> head layout [b,h,s,hd]
    dim3 gproj(D_/128, M_/128, 1);
    gemm_mma<128,1,false><<<gproj, 256, SM128>>>(x, wq, bq, q, nullptr, nullptr,
        D_, D_, D_, 0, 0, 0, 0, 1.0f);
    gemm_mma<128,1,false><<<gproj, 256, SM128>>>(x, wk, bk, k, nullptr, nullptr,
        D_, D_, D_, 0, 0, 0, 0, 1.0f);
    gemm_mma<128,1,false><<<gproj, 256, SM128>>>(x, wv, bv, v, nullptr, nullptr,
        D_, D_, D_, 0, 0, 0, 0, 1.0f);

    // 2) transpose V for the PV GEMM
    vtrans<<<dim3(S_/32, HD_/32, G_), dim3(32, 8)>>>(v, vt);

    // 3) scores = Q K^T / 8
    gemm_mma<128,0,false><<<dim3(S_/128, S_/128, G_), 256, SM128>>>(
        q, k, nullptr, p, nullptr, nullptr,
        HD_, HD_, HD_, S_, (long)S_*HD_, (long)S_*HD_, (long)S_*S_, 0.125f);

    // 4) softmax row stats
    rowstats<<<G_*S_, 256>>>(p, mx, iv);

    // 5) O = softmax(P) V  (normalization fused into A staging)
    gemm_mma<64,0,true><<<dim3(1, S_/128, G_), 256, SM64>>>(
        p, vt, nullptr, oh, mx, iv,
        S_, S_, S_, HD_, (long)S_*S_, (long)HD_*S_, (long)S_*HD_, 1.0f);

    // 6) Gram-Schmidt exclusion + relayout
    exclude_gs<<<(G_*S_)/8, 256>>>(oh, v, ob);

    // 7) output projection -> d_out
    gemm_mma<128,0,false><<<dim3(D_/128, M_/128, 1), 256, SM128>>>(
        ob, wo, bo, out, nullptr, nullptr,
        D_, D_, D_, D_, 0, 0, 0, 1.0f);
}

// round 6
// speedup vs baseline: 2.6918x; 1.5240x over previous
#include <cuda_runtime.h>
#include <cuda_bf16.h>
#include <cstdint>

#define B_   2
#define S_   2048
#define D_   1024
#define H_   16
#define HD_  64
#define M_   (B_*S_)     // 4096
#define G_   (B_*H_)     // 32

// ---- scratch (static device arrays; no allocation allowed) ----
__device__ float g_q [(size_t)G_*S_*HD_];   // [b,h,s,hd]
__device__ float g_k [(size_t)G_*S_*HD_];
__device__ float g_v [(size_t)G_*S_*HD_];
__device__ float g_ob[(size_t)M_*D_];       // post-exclusion, [b,s,d]

// ============================================================================
// MMA / ldmatrix helpers (baseline PTX, compiles for sm_103)
// ============================================================================
__device__ __forceinline__ uint32_t smem_u32(const void* p) {
    uint32_t a;
    asm("{ .reg .u64 t; cvta.to.shared.u64 t, %1; cvt.u32.u64 %0, t; }"
        : "=r"(a) : "l"(p));
    return a;
}

__device__ __forceinline__ void ldm_x4(uint32_t* r, uint32_t addr) {
    asm volatile("ldmatrix.sync.aligned.m8n8.x4.shared.b16 {%0,%1,%2,%3}, [%4];"
        : "=r"(r[0]), "=r"(r[1]), "=r"(r[2]), "=r"(r[3]) : "r"(addr));
}

__device__ __forceinline__ void ldm_x4_t(uint32_t* r, uint32_t addr) {
    asm volatile("ldmatrix.sync.aligned.m8n8.x4.trans.shared.b16 {%0,%1,%2,%3}, [%4];"
        : "=r"(r[0]), "=r"(r[1]), "=r"(r[2]), "=r"(r[3]) : "r"(addr));
}

__device__ __forceinline__ void mma16816(float* c, const uint32_t* a,
                                         uint32_t b0, uint32_t b1) {
    asm volatile(
        "mma.sync.aligned.m16n8k16.row.col.f32.bf16.bf16.f32 "
        "{%0,%1,%2,%3}, {%4,%5,%6,%7}, {%8,%9}, {%0,%1,%2,%3};"
        : "+f"(c[0]), "+f"(c[1]), "+f"(c[2]), "+f"(c[3])
        : "r"(a[0]), "r"(a[1]), "r"(a[2]), "r"(a[3]), "r"(b0), "r"(b1));
}

__device__ __forceinline__ uint32_t packbf(float x, float y) {
    __nv_bfloat162 t;
    t.x = __float2bfloat16_rn(x);
    t.y = __float2bfloat16_rn(y);
    return *(uint32_t*)&t;
}
__device__ __forceinline__ uint32_t packbf_lo(float x, float y, uint32_t hi) {
    __nv_bfloat162 h = *(__nv_bfloat162*)&hi;
    return packbf(x - __bfloat162float(h.x), y - __bfloat162float(h.y));
}

// ============================================================================
// Stage a 128x64 fp32 tile (row stride 64) -> hi/lo bf16 smem, 128B rows,
// 16B chunk swizzle: phys = chunk ^ (row & 7).  Conflict-free STS.128 and
// conflict-free 8-row ldmatrix (normal and trans).
// ============================================================================
__device__ __forceinline__ void stage128x64(const float* __restrict__ src,
                                            char* hi, char* lo, int tid)
{
    #pragma unroll
    for (int i = 0; i < 4; ++i) {
        int idx = tid + i * 256;
        int row = idx >> 3, c = idx & 7;
        const float* p = src + row * 64 + c * 8;
        float4 v0 = *(const float4*)p;
        float4 v1 = *(const float4*)(p + 4);
        uint32_t hw0 = packbf(v0.x, v0.y), hw1 = packbf(v0.z, v0.w);
        uint32_t hw2 = packbf(v1.x, v1.y), hw3 = packbf(v1.z, v1.w);
        uint32_t lw0 = packbf_lo(v0.x, v0.y, hw0), lw1 = packbf_lo(v0.z, v0.w, hw1);
        uint32_t lw2 = packbf_lo(v1.x, v1.y, hw2), lw3 = packbf_lo(v1.z, v1.w, hw3);
        uint32_t off = (uint32_t)(row * 128) + (uint32_t)(((c ^ (row & 7)) << 4));
        *(uint4*)(hi + off) = make_uint4(hw0, hw1, hw2, hw3);
        *(uint4*)(lo + off) = make_uint4(lw0, lw1, lw2, lw3);
    }
}

// ============================================================================
// Fused attention: scores + online softmax + PV + 1/l + Gram-Schmidt exclusion.
// Grid (S/128, G). 8 warps; warp owns 16 Q rows x full KV block.
// bf16 2-term split on both GEMMs (3 MMAs per product).
// ============================================================================
__global__ void __launch_bounds__(256, 1)
fused_attn(const float* __restrict__ Q, const float* __restrict__ K,
           const float* __restrict__ V, float* __restrict__ OB)
{
    extern __shared__ char sm[];
    const int tid = threadIdx.x;
    const int wid = tid >> 5;
    const int l   = tid & 31;
    const int g   = blockIdx.y;
    const int m0  = blockIdx.x * 128;
    const int wm  = wid * 16;

    const float* Qg = Q + ((long)g * S_ + m0) * HD_;
    const float* Kg = K + (long)g * S_ * HD_;
    const float* Vg = V + (long)g * S_ * HD_;

    char* qhi = sm;             char* qlo = sm + 16384;
    char* khi = sm + 32768;     char* klo = sm + 49152;
    char* vhi = sm + 65536;     char* vlo = sm + 81920;
    const uint32_t qb = smem_u32(qhi);
    const uint32_t kb = smem_u32(khi);
    const uint32_t vb = smem_u32(vhi);

    stage128x64(Qg, qhi, qlo, tid);

    float oacc[8][4];
    #pragma unroll
    for (int i = 0; i < 8; ++i)
        #pragma unroll
        for (int j = 0; j < 4; ++j) oacc[i][j] = 0.0f;
    float mrun[2] = {-1e30f, -1e30f};
    float lsum[2] = {0.0f, 0.0f};

    // lane-constant address pieces
    const int aR = wm + (l & 15);                 // A rows (Q)
    const int bR = ((l >> 4) & 1) * 8 + (l & 7);  // B rows (K), + nb*16
    const int bC = (l >> 3) & 1;
    const int vR = (l & 15);                      // V rows, + kt*16
    const int vC = (l >> 4);

    for (int j = 0; j < 16; ++j) {
        __syncthreads();
        stage128x64(Kg + (long)j * 128 * 64, khi, klo, tid);
        stage128x64(Vg + (long)j * 128 * 64, vhi, vlo, tid);
        __syncthreads();

        // ---- S = Q K^T : warp tile 16 x 128 ----
        float sacc[16][4];
        #pragma unroll
        for (int i = 0; i < 16; ++i)
            #pragma unroll
            for (int c = 0; c < 4; ++c) sacc[i][c] = 0.0f;

        #pragma unroll
        for (int ks = 0; ks < 4; ++ks) {
            uint32_t ah[4], al[4];
            {
                uint32_t off = (uint32_t)(aR * 128)
                             + (uint32_t)((((ks * 2 + (l >> 4)) ^ (aR & 7)) << 4));
                ldm_x4(ah, qb + off);
                ldm_x4(al, qb + 16384 + off);
            }
            #pragma unroll
            for (int nb = 0; nb < 8; ++nb) {
                uint32_t bh[4], bl[4];
                int row = nb * 16 + bR;
                uint32_t off = (uint32_t)(row * 128)
                             + (uint32_t)((((ks * 2 + bC) ^ (row & 7)) << 4));
                ldm_x4(bh, kb + off);
                ldm_x4(bl, kb + 16384 + off);
                #pragma unroll
                for (int nt2 = 0; nt2 < 2; ++nt2) {
                    float* c = sacc[nb * 2 + nt2];
                    mma16816(c, ah, bh[nt2*2], bh[nt2*2+1]);
                    mma16816(c, ah, bl[nt2*2], bl[nt2*2+1]);
                    mma16816(c, al, bh[nt2*2], bh[nt2*2+1]);
                }
            }
        }

        // ---- online softmax (rows: h=0 -> l>>2, h=1 -> +8) ----
        float mnew[2] = {-1e30f, -1e30f};
        #pragma unroll
        for (int nt = 0; nt < 16; ++nt) {
            #pragma unroll
            for (int c = 0; c < 4; ++c) sacc[nt][c] *= 0.125f;
            mnew[0] = fmaxf(mnew[0], fmaxf(sacc[nt][0], sacc[nt][1]));
            mnew[1] = fmaxf(mnew[1], fmaxf(sacc[nt][2], sacc[nt][3]));
        }
        #pragma unroll
        for (int h = 0; h < 2; ++h) {
            mnew[h] = fmaxf(mnew[h], __shfl_xor_sync(0xffffffffu, mnew[h], 1));
            mnew[h] = fmaxf(mnew[h], __shfl_xor_sync(0xffffffffu, mnew[h], 2));
        }
        float corr[2];
        #pragma unroll
        for (int h = 0; h < 2; ++h) {
            float mi = fmaxf(mrun[h], mnew[h]);
            corr[h] = __expf(mrun[h] - mi);
            mrun[h] = mi;
            lsum[h] *= corr[h];
        }
        float rs[2] = {0.0f, 0.0f};
        #pragma unroll
        for (int nt = 0; nt < 16; ++nt) {
            sacc[nt][0] = __expf(sacc[nt][0] - mrun[0]);
            sacc[nt][1] = __expf(sacc[nt][1] - mrun[0]);
            sacc[nt][2] = __expf(sacc[nt][2] - mrun[1]);
            sacc[nt][3] = __expf(sacc[nt][3] - mrun[1]);
            rs[0] += sacc[nt][0] + sacc[nt][1];
            rs[1] += sacc[nt][2] + sacc[nt][3];
        }
        #pragma unroll
        for (int h = 0; h < 2; ++h) {
            rs[h] += __shfl_xor_sync(0xffffffffu, rs[h], 1);
            rs[h] += __shfl_xor_sync(0xffffffffu, rs[h], 2);
            lsum[h] += rs[h];
        }
        #pragma unroll
        for (int nt = 0; nt < 8; ++nt) {
            oacc[nt][0] *= corr[0]; oacc[nt][1] *= corr[0];
            oacc[nt][2] *= corr[1]; oacc[nt][3] *= corr[1];
        }

        // ---- O += P V  (P from sacc regs; V via ldmatrix.trans) ----
        #pragma unroll
        for (int kt = 0; kt < 8; ++kt) {
            uint32_t ph[4], pl[4];
            ph[0] = packbf(sacc[2*kt][0],   sacc[2*kt][1]);
            ph[1] = packbf(sacc[2*kt][2],   sacc[2*kt][3]);
            ph[2] = packbf(sacc[2*kt+1][0], sacc[2*kt+1][1]);
            ph[3] = packbf(sacc[2*kt+1][2], sacc[2*kt+1][3]);
            pl[0] = packbf_lo(sacc[2*kt][0],   sacc[2*kt][1],   ph[0]);
            pl[1] = packbf_lo(sacc[2*kt][2],   sacc[2*kt][3],   ph[1]);
            pl[2] = packbf_lo(sacc[2*kt+1][0], sacc[2*kt+1][1], ph[2]);
            pl[3] = packbf_lo(sacc[2*kt+1][2], sacc[2*kt+1][3], ph[3]);
            #pragma unroll
            for (int np = 0; np < 4; ++np) {
                uint32_t vh[4], vl[4];
                int row = kt * 16 + vR;
                uint32_t off = (uint32_t)(row * 128)
                             + (uint32_t)((((np * 2 + vC) ^ (row & 7)) << 4));
                ldm_x4_t(vh, vb + off);
                ldm_x4_t(vl, vb + 16384 + off);
                #pragma unroll
                for (int d2 = 0; d2 < 2; ++d2) {
                    float* c = oacc[np * 2 + d2];
                    mma16816(c, ph, vh[d2*2], vh[d2*2+1]);
                    mma16816(c, ph, vl[d2*2], vl[d2*2+1]);
                    mma16816(c, pl, vh[d2*2], vh[d2*2+1]);
                }
            }
        }
    }

    // ---- finalize: 1/l, Gram-Schmidt exclusion, store [b,s,d] ----
    float inv[2] = {1.0f / lsum[0], 1.0f / lsum[1]};
    #pragma unroll
    for (int nt = 0; nt < 8; ++nt) {
        oacc[nt][0] *= inv[0]; oacc[nt][1] *= inv[0];
        oacc[nt][2] *= inv[1]; oacc[nt][3] *= inv[1];
    }

    const int bb = g >> 4, hh = g & 15;
    #pragma unroll
    for (int half = 0; half < 2; ++half) {
        int grow = m0 + wm + (l >> 2) + half * 8;
        const float* vr = Vg + (long)grow * HD_;
        float vv[16];
        float dov = 0.0f, dvv = 0.0f;
        #pragma unroll
        for (int nt = 0; nt < 8; ++nt) {
            float2 t = *(const float2*)(vr + nt * 8 + (l & 3) * 2);
            vv[2*nt] = t.x; vv[2*nt+1] = t.y;
            float o0 = oacc[nt][half*2], o1 = oacc[nt][half*2+1];
            dov += o0 * t.x + o1 * t.y;
            dvv += t.x * t.x + t.y * t.y;
        }
        dov += __shfl_xor_sync(0xffffffffu, dov, 1);
        dov += __shfl_xor_sync(0xffffffffu, dov, 2);
        dvv += __shfl_xor_sync(0xffffffffu, dvv, 1);
        dvv += __shfl_xor_sync(0xffffffffu, dvv, 2);
        float al_ = dov / (dvv + 1e-8f);
        float* ob = OB + ((long)(bb * S_ + grow) * D_ + hh * HD_);
        #pragma unroll
        for (int nt = 0; nt < 8; ++nt) {
            float2 r;
            r.x = oacc[nt][half*2]   - al_ * vv[2*nt];
            r.y = oacc[nt][half*2+1] - al_ * vv[2*nt+1];
            *(float2*)(ob + nt * 8 + (l & 3) * 2) = r;
        }
    }
}

// ============================================================================
// Staging for GEMM: fp32 gmem (K-contiguous rows) -> hi/lo bf16 swizzled smem.
// Tile rows x 32 k-elems; smem row = 64 B; chunk swizzle c ^ ((row>>1)&3).
// ============================================================================
template<int ITEMS>
__device__ __forceinline__ void stage_load(float4 (*pf)[2],
    const float* __restrict__ src, int lds, int kc, int tid)
{
    #pragma unroll
    for (int i = 0; i < ITEMS; ++i) {
        int idx = tid + i * 256;
        int row = idx >> 2, ci = idx & 3;
        const float* p = src + (long)row * lds + kc + ci * 8;
        pf[i][0] = *(const float4*)p;
        pf[i][1] = *(const float4*)(p + 4);
    }
}

template<int ITEMS>
__device__ __forceinline__ void stage_store(float4 (*pf)[2], char* hi, char* lo, int tid)
{
    #pragma unroll
    for (int i = 0; i < ITEMS; ++i) {
        int idx = tid + i * 256;
        int row = idx >> 2, ci = idx & 3;
        float f[8] = { pf[i][0].x, pf[i][0].y, pf[i][0].z, pf[i][0].w,
                       pf[i][1].x, pf[i][1].y, pf[i][1].z, pf[i][1].w };
        uint32_t hw[4], lw[4];
        #pragma unroll
        for (int j = 0; j < 4; ++j) {
            hw[j] = packbf(f[2*j], f[2*j+1]);
            lw[j] = packbf_lo(f[2*j], f[2*j+1], hw[j]);
        }
        uint32_t off = (uint32_t)(row * 64) + (uint32_t)(((ci ^ ((row >> 1) & 3)) << 4));
        *(uint4*)(hi + off) = make_uint4(hw[0], hw[1], hw[2], hw[3]);
        *(uint4*)(lo + off) = make_uint4(lw[0], lw[1], lw[2], lw[3]);
    }
}

// ============================================================================
// HMMA GEMM (projections / output): C = A W^T + bias. BM=128, BN=128, BK=32.
// bf16 2-term split. Double-buffered smem + register prefetch.
// MODE 0: flat store. MODE 1: [b,h,s,hd] head store.
// ============================================================================
template<int MODE>
__global__ void __launch_bounds__(256, 1)
gemm_mma(const float* __restrict__ A, const float* __restrict__ W,
         const float* __restrict__ bias, float* __restrict__ C,
         int K, int lda, int ldw, int ldc)
{
    extern __shared__ char smem[];
    constexpr int ABYTES = 128 * 64;
    constexpr int BBYTES = 128 * 64;
    constexpr int STG    = 2 * ABYTES + 2 * BBYTES;

    const int tid = threadIdx.x;
    const int wid = tid >> 5;
    const int l   = tid & 31;
    const int m0  = blockIdx.y * 128;
    const int n0  = blockIdx.x * 128;
    const int wm  = (wid / 4) * 64;
    const int wn  = (wid % 4) * 32;

    const float* At = A + (long)m0 * lda;
    const float* Wt = W + (long)n0 * ldw;

    const int aRow = (l & 15);
    const int aCk  = (l >> 4);
    const int bRow = ((l >> 4) & 1) * 8 + (l & 7);
    const int bCk  = (l >> 3) & 1;

    int raRow[4], raSwz[4];
    #pragma unroll
    for (int mt = 0; mt < 4; ++mt) {
        raRow[mt] = wm + mt * 16 + aRow;
        raSwz[mt] = (raRow[mt] >> 1) & 3;
    }
    int rbRow[2], rbSwz[2];
    #pragma unroll
    for (int nb = 0; nb < 2; ++nb) {
        rbRow[nb] = wn + nb * 16 + bRow;
        rbSwz[nb] = (rbRow[nb] >> 1) & 3;
    }

    float acc[4][4][4];
    #pragma unroll
    for (int a = 0; a < 4; ++a)
        #pragma unroll
        for (int b = 0; b < 4; ++b)
            #pragma unroll
            for (int c = 0; c < 4; ++c) acc[a][b][c] = 0.0f;

    const uint32_t sb = smem_u32(smem);
    const int nch = K / 32;

    float4 pfA[2][2], pfB[2][2];
    stage_load<2>(pfA, At, lda, 0, tid);
    stage_load<2>(pfB, Wt, ldw, 0, tid);

    for (int c = 0; c < nch; ++c) {
        char* buf = smem + (c & 1) * STG;
        stage_store<2>(pfA, buf,              buf + ABYTES, tid);
        stage_store<2>(pfB, buf + 2*ABYTES,   buf + 2*ABYTES + BBYTES, tid);
        __syncthreads();

        if (c + 1 < nch) {
            stage_load<2>(pfA, At, lda, (c + 1) * 32, tid);
            stage_load<2>(pfB, Wt, ldw, (c + 1) * 32, tid);
        }

        const uint32_t ahi = sb + (c & 1) * STG;
        const uint32_t alo = ahi + ABYTES;
        const uint32_t bhi = alo + ABYTES;
        const uint32_t blo = bhi + BBYTES;

        #pragma unroll
        for (int ks = 0; ks < 2; ++ks) {
            uint32_t ah[4][4], al[4][4], bh[2][4], bl[2][4];
            #pragma unroll
            for (int mt = 0; mt < 4; ++mt) {
                uint32_t off = (uint32_t)(raRow[mt] * 64)
                             + (uint32_t)((((2*ks + aCk) ^ raSwz[mt]) << 4));
                ldm_x4(ah[mt], ahi + off);
                ldm_x4(al[mt], alo + off);
            }
            #pragma unroll
            for (int nb = 0; nb < 2; ++nb) {
                uint32_t off = (uint32_t)(rbRow[nb] * 64)
                             + (uint32_t)((((2*ks + bCk) ^ rbSwz[nb]) << 4));
                ldm_x4(bh[nb], bhi + off);
                ldm_x4(bl[nb], blo + off);
            }
            #pragma unroll
            for (int mt = 0; mt < 4; ++mt) {
                #pragma unroll
                for (int nt = 0; nt < 4; ++nt) {
                    const uint32_t* pbh = &bh[nt >> 1][(nt & 1) * 2];
                    const uint32_t* pbl = &bl[nt >> 1][(nt & 1) * 2];
                    mma16816(acc[mt][nt], ah[mt], pbh[0], pbh[1]);
                    mma16816(acc[mt][nt], ah[mt], pbl[0], pbl[1]);
                    mma16816(acc[mt][nt], al[mt], pbh[0], pbh[1]);
                }
            }
        }
        __syncthreads();
    }

    #pragma unroll
    for (int mt = 0; mt < 4; ++mt) {
        #pragma unroll
        for (int nt = 0; nt < 4; ++nt) {
            int n = n0 + wn + nt * 8 + (l & 3) * 2;
            float2 bb = *(const float2*)(bias + n);
            #pragma unroll
            for (int half = 0; half < 2; ++half) {
                int m = m0 + wm + mt * 16 + (l >> 2) + half * 8;
                float2 r;
                r.x = acc[mt][nt][half*2]   + bb.x;
                r.y = acc[mt][nt][half*2+1] + bb.y;
                if (MODE == 0) {
                    *(float2*)(C + (long)m * ldc + n) = r;
                } else {
                    int b2 = m >> 11, s = m & 2047;
                    int h = n >> 6, hd = n & 63;
                    *(float2*)(C + (((long)(b2 * H_ + h) * S_ + s) * HD_ + hd)) = r;
                }
            }
        }
    }
}

// ============================================================================
extern "C" void kernel_launch(void* const* d_in, const int* in_sizes, int n_in,
                              void* d_out, int out_size)
{
    const float* x  = (const float*)d_in[0];
    const float* wq = (const float*)d_in[1];
    const float* bq = (const float*)d_in[2];
    const float* wk = (const float*)d_in[3];
    const float* bk = (const float*)d_in[4];
    const float* wv = (const float*)d_in[5];
    const float* bv = (const float*)d_in[6];
    const float* wo = (const float*)d_in[7];
    const float* bo = (const float*)d_in[8];
    float* out = (float*)d_out;

    float *q, *k, *v, *ob;
    cudaGetSymbolAddress((void**)&q,  g_q);
    cudaGetSymbolAddress((void**)&k,  g_k);
    cudaGetSymbolAddress((void**)&v,  g_v);
    cudaGetSymbolAddress((void**)&ob, g_ob);

    const int SMG = 2 * (2*128*64 + 2*128*64);   // 65536
    const int SMF = 6 * 16384;                    // 98304
    cudaFuncSetAttribute(gemm_mma<1>, cudaFuncAttributeMaxDynamicSharedMemorySize, SMG);
    cudaFuncSetAttribute(gemm_mma<0>, cudaFuncAttributeMaxDynamicSharedMemorySize, SMG);
    cudaFuncSetAttribute(fused_attn,  cudaFuncAttributeMaxDynamicSharedMemorySize, SMF);

    // 1) Q/K/V projections -> head layout [b,h,s,hd]
    dim3 gproj(D_/128, M_/128, 1);
    gemm_mma<1><<<gproj, 256, SMG>>>(x, wq, bq, q, D_, D_, D_, 0);
    gemm_mma<1><<<gproj, 256, SMG>>>(x, wk, bk, k, D_, D_, D_, 0);
    gemm_mma<1><<<gproj, 256, SMG>>>(x, wv, bv, v, D_, D_, D_, 0);

    // 2) fused attention + softmax + exclusion -> ob [b,s,d]
    fused_attn<<<dim3(S_/128, G_), 256, SMF>>>(q, k, v, ob);

    // 3) output projection -> d_out
    gemm_mma<0><<<dim3(D_/128, M_/128, 1), 256, SMG>>>(ob, wo, bo, out, D_, D_, D_, D_);
}

// round 7
// speedup vs baseline: 2.7399x; 1.0179x over previous
#include <cuda_runtime.h>
#include <cuda_bf16.h>
#include <cstdint>

#define B_   2
#define S_   2048
#define D_   1024
#define H_   16
#define HD_  64
#define M_   (B_*S_)     // 4096
#define G_   (B_*H_)     // 32

// ---- scratch (static device arrays; no allocation allowed) ----
__device__ float g_q [(size_t)G_*S_*HD_];   // [b,h,s,hd]
__device__ float g_k [(size_t)G_*S_*HD_];
__device__ float g_v [(size_t)G_*S_*HD_];
__device__ float g_ob[(size_t)M_*D_];       // post-exclusion, [b,s,d]

// ============================================================================
// MMA / ldmatrix helpers (baseline PTX, compiles for sm_103)
// ============================================================================
__device__ __forceinline__ uint32_t smem_u32(const void* p) {
    uint32_t a;
    asm("{ .reg .u64 t; cvta.to.shared.u64 t, %1; cvt.u32.u64 %0, t; }"
        : "=r"(a) : "l"(p));
    return a;
}

__device__ __forceinline__ void ldm_x4(uint32_t* r, uint32_t addr) {
    asm volatile("ldmatrix.sync.aligned.m8n8.x4.shared.b16 {%0,%1,%2,%3}, [%4];"
        : "=r"(r[0]), "=r"(r[1]), "=r"(r[2]), "=r"(r[3]) : "r"(addr));
}

__device__ __forceinline__ void ldm_x4_t(uint32_t* r, uint32_t addr) {
    asm volatile("ldmatrix.sync.aligned.m8n8.x4.trans.shared.b16 {%0,%1,%2,%3}, [%4];"
        : "=r"(r[0]), "=r"(r[1]), "=r"(r[2]), "=r"(r[3]) : "r"(addr));
}

__device__ __forceinline__ void mma16816(float* c, const uint32_t* a,
                                         uint32_t b0, uint32_t b1) {
    asm volatile(
        "mma.sync.aligned.m16n8k16.row.col.f32.bf16.bf16.f32 "
        "{%0,%1,%2,%3}, {%4,%5,%6,%7}, {%8,%9}, {%0,%1,%2,%3};"
        : "+f"(c[0]), "+f"(c[1]), "+f"(c[2]), "+f"(c[3])
        : "r"(a[0]), "r"(a[1]), "r"(a[2]), "r"(a[3]), "r"(b0), "r"(b1));
}

__device__ __forceinline__ uint32_t packbf(float x, float y) {
    __nv_bfloat162 t;
    t.x = __float2bfloat16_rn(x);
    t.y = __float2bfloat16_rn(y);
    return *(uint32_t*)&t;
}
__device__ __forceinline__ uint32_t packbf_lo(float x, float y, uint32_t hi) {
    __nv_bfloat162 h = *(__nv_bfloat162*)&hi;
    return packbf(x - __bfloat162float(h.x), y - __bfloat162float(h.y));
}

// ============================================================================
// Fused-attn staging: 128x64 fp32 tile (row stride 64) -> hi/lo bf16 smem,
// 128B rows, 16B chunk swizzle phys = chunk ^ (row & 7).
// Split into LDG (to regs) and CVT+STS halves for software pipelining.
// ============================================================================
__device__ __forceinline__ void ldg_tile(float4 (*pf)[2],
    const float* __restrict__ src, int tid)
{
    #pragma unroll
    for (int i = 0; i < 4; ++i) {
        int idx = tid + i * 256;
        int row = idx >> 3, c = idx & 7;
        const float* p = src + row * 64 + c * 8;
        pf[i][0] = *(const float4*)p;
        pf[i][1] = *(const float4*)(p + 4);
    }
}

__device__ __forceinline__ void cvt_store_tile(float4 (*pf)[2],
    char* hi, char* lo, int tid)
{
    #pragma unroll
    for (int i = 0; i < 4; ++i) {
        int idx = tid + i * 256;
        int row = idx >> 3, c = idx & 7;
        float4 v0 = pf[i][0], v1 = pf[i][1];
        uint32_t hw0 = packbf(v0.x, v0.y), hw1 = packbf(v0.z, v0.w);
        uint32_t hw2 = packbf(v1.x, v1.y), hw3 = packbf(v1.z, v1.w);
        uint32_t lw0 = packbf_lo(v0.x, v0.y, hw0), lw1 = packbf_lo(v0.z, v0.w, hw1);
        uint32_t lw2 = packbf_lo(v1.x, v1.y, hw2), lw3 = packbf_lo(v1.z, v1.w, hw3);
        uint32_t off = (uint32_t)(row * 128) + (uint32_t)(((c ^ (row & 7)) << 4));
        *(uint4*)(hi + off) = make_uint4(hw0, hw1, hw2, hw3);
        *(uint4*)(lo + off) = make_uint4(lw0, lw1, lw2, lw3);
    }
}

// ============================================================================
// Fused attention: scores + online softmax + PV + 1/l + Gram-Schmidt exclusion.
// Grid (S/128, G). 8 warps; warp owns 16 Q rows x full KV block.
// Double-buffered K/V smem stages; LDG prefetch overlapped with MMA phases.
// smem: Q hi/lo 32KB | K hi/lo x2 64KB | V hi/lo x2 64KB = 160 KB.
// ============================================================================
__global__ void __launch_bounds__(256, 1)
fused_attn(const float* __restrict__ Q, const float* __restrict__ K,
           const float* __restrict__ V, float* __restrict__ OB)
{
    extern __shared__ char sm[];
    const int tid = threadIdx.x;
    const int wid = tid >> 5;
    const int l   = tid & 31;
    const int g   = blockIdx.y;
    const int m0  = blockIdx.x * 128;
    const int wm  = wid * 16;

    const float* Qg = Q + ((long)g * S_ + m0) * HD_;
    const float* Kg = K + (long)g * S_ * HD_;
    const float* Vg = V + (long)g * S_ * HD_;

    const uint32_t sb = smem_u32(sm);
    const uint32_t qb = sb;                 // Q hi @0, lo @16384
    // K buffers: hi @32768 + st*32768, lo = hi + 16384
    // V buffers: hi @98304 + st*32768, lo = hi + 16384

    float4 pfK[4][2], pfV[4][2];

    // prologue: stage Q and block-0 K/V
    {
        ldg_tile(pfK, Kg, tid);
        ldg_tile(pfV, Vg, tid);
        // Q direct: load + cvt + store
        float4 pfQ[4][2];
        ldg_tile(pfQ, Qg, tid);
        cvt_store_tile(pfQ, sm, sm + 16384, tid);
        cvt_store_tile(pfK, sm + 32768, sm + 49152, tid);
        cvt_store_tile(pfV, sm + 98304, sm + 114688, tid);
    }
    __syncthreads();

    float oacc[8][4];
    #pragma unroll
    for (int i = 0; i < 8; ++i)
        #pragma unroll
        for (int j = 0; j < 4; ++j) oacc[i][j] = 0.0f;
    float mrun[2] = {-1e30f, -1e30f};
    float lsum[2] = {0.0f, 0.0f};

    // lane-constant address pieces
    const int aR = wm + (l & 15);                 // A rows (Q)
    const int bR = ((l >> 4) & 1) * 8 + (l & 7);  // B rows (K), + nb*16
    const int bC = (l >> 3) & 1;
    const int vR = (l & 15);                      // V rows, + kt*16
    const int vC = (l >> 4);

    for (int j = 0; j < 16; ++j) {
        const int cur = j & 1, nxt = cur ^ 1;
        const uint32_t kb = sb + 32768 + cur * 32768;
        const uint32_t vb = sb + 98304 + cur * 32768;

        if (j < 15) ldg_tile(pfK, Kg + (long)(j + 1) * 8192, tid);

        // ---- S = Q K^T : warp tile 16 x 128 ----
        float sacc[16][4];
        #pragma unroll
        for (int i = 0; i < 16; ++i)
            #pragma unroll
            for (int c = 0; c < 4; ++c) sacc[i][c] = 0.0f;

        #pragma unroll
        for (int ks = 0; ks < 4; ++ks) {
            uint32_t ah[4], al[4];
            {
                uint32_t off = (uint32_t)(aR * 128)
                             + (uint32_t)((((ks * 2 + (l >> 4)) ^ (aR & 7)) << 4));
                ldm_x4(ah, qb + off);
                ldm_x4(al, qb + 16384 + off);
            }
            #pragma unroll
            for (int nb = 0; nb < 8; ++nb) {
                uint32_t bh[4], bl[4];
                int row = nb * 16 + bR;
                uint32_t off = (uint32_t)(row * 128)
                             + (uint32_t)((((ks * 2 + bC) ^ (row & 7)) << 4));
                ldm_x4(bh, kb + off);
                ldm_x4(bl, kb + 16384 + off);
                #pragma unroll
                for (int nt2 = 0; nt2 < 2; ++nt2) {
                    float* c = sacc[nb * 2 + nt2];
                    mma16816(c, ah, bh[nt2*2], bh[nt2*2+1]);
                    mma16816(c, ah, bl[nt2*2], bl[nt2*2+1]);
                    mma16816(c, al, bh[nt2*2], bh[nt2*2+1]);
                }
            }
        }

        // ---- online softmax (rows: h=0 -> l>>2, h=1 -> +8) ----
        float mnew[2] = {-1e30f, -1e30f};
        #pragma unroll
        for (int nt = 0; nt < 16; ++nt) {
            #pragma unroll
            for (int c = 0; c < 4; ++c) sacc[nt][c] *= 0.125f;
            mnew[0] = fmaxf(mnew[0], fmaxf(sacc[nt][0], sacc[nt][1]));
            mnew[1] = fmaxf(mnew[1], fmaxf(sacc[nt][2], sacc[nt][3]));
        }
        #pragma unroll
        for (int h = 0; h < 2; ++h) {
            mnew[h] = fmaxf(mnew[h], __shfl_xor_sync(0xffffffffu, mnew[h], 1));
            mnew[h] = fmaxf(mnew[h], __shfl_xor_sync(0xffffffffu, mnew[h], 2));
        }
        float corr[2];
        #pragma unroll
        for (int h = 0; h < 2; ++h) {
            float mi = fmaxf(mrun[h], mnew[h]);
            corr[h] = __expf(mrun[h] - mi);
            mrun[h] = mi;
            lsum[h] *= corr[h];
        }
        float rs[2] = {0.0f, 0.0f};
        #pragma unroll
        for (int nt = 0; nt < 16; ++nt) {
            sacc[nt][0] = __expf(sacc[nt][0] - mrun[0]);
            sacc[nt][1] = __expf(sacc[nt][1] - mrun[0]);
            sacc[nt][2] = __expf(sacc[nt][2] - mrun[1]);
            sacc[nt][3] = __expf(sacc[nt][3] - mrun[1]);
            rs[0] += sacc[nt][0] + sacc[nt][1];
            rs[1] += sacc[nt][2] + sacc[nt][3];
        }
        #pragma unroll
        for (int h = 0; h < 2; ++h) {
            rs[h] += __shfl_xor_sync(0xffffffffu, rs[h], 1);
            rs[h] += __shfl_xor_sync(0xffffffffu, rs[h], 2);
            lsum[h] += rs[h];
        }
        #pragma unroll
        for (int nt = 0; nt < 8; ++nt) {
            oacc[nt][0] *= corr[0]; oacc[nt][1] *= corr[0];
            oacc[nt][2] *= corr[1]; oacc[nt][3] *= corr[1];
        }

        // store next K tile to the inactive buffer; prefetch next V
        if (j < 15) {
            cvt_store_tile(pfK, sm + 32768 + nxt * 32768,
                                sm + 49152 + nxt * 32768, tid);
            ldg_tile(pfV, Vg + (long)(j + 1) * 8192, tid);
        }

        // ---- O += P V  (P from sacc regs; V via ldmatrix.trans) ----
        #pragma unroll
        for (int kt = 0; kt < 8; ++kt) {
            uint32_t ph[4], pl[4];
            ph[0] = packbf(sacc[2*kt][0],   sacc[2*kt][1]);
            ph[1] = packbf(sacc[2*kt][2],   sacc[2*kt][3]);
            ph[2] = packbf(sacc[2*kt+1][0], sacc[2*kt+1][1]);
            ph[3] = packbf(sacc[2*kt+1][2], sacc[2*kt+1][3]);
            pl[0] = packbf_lo(sacc[2*kt][0],   sacc[2*kt][1],   ph[0]);
            pl[1] = packbf_lo(sacc[2*kt][2],   sacc[2*kt][3],   ph[1]);
            pl[2] = packbf_lo(sacc[2*kt+1][0], sacc[2*kt+1][1], ph[2]);
            pl[3] = packbf_lo(sacc[2*kt+1][2], sacc[2*kt+1][3], ph[3]);
            #pragma unroll
            for (int np = 0; np < 4; ++np) {
                uint32_t vh[4], vl[4];
                int row = kt * 16 + vR;
                uint32_t off = (uint32_t)(row * 128)
                             + (uint32_t)((((np * 2 + vC) ^ (row & 7)) << 4));
                ldm_x4_t(vh, vb + off);
                ldm_x4_t(vl, vb + 16384 + off);
                #pragma unroll
                for (int d2 = 0; d2 < 2; ++d2) {
                    float* c = oacc[np * 2 + d2];
                    mma16816(c, ph, vh[d2*2], vh[d2*2+1]);
                    mma16816(c, ph, vl[d2*2], vl[d2*2+1]);
                    mma16816(c, pl, vh[d2*2], vh[d2*2+1]);
                }
            }
        }

        if (j < 15)
            cvt_store_tile(pfV, sm + 98304 + nxt * 32768,
                                sm + 114688 + nxt * 32768, tid);
        __syncthreads();
    }

    // ---- finalize: 1/l, Gram-Schmidt exclusion, store [b,s,d] ----
    float inv[2] = {1.0f / lsum[0], 1.0f / lsum[1]};
    #pragma unroll
    for (int nt = 0; nt < 8; ++nt) {
        oacc[nt][0] *= inv[0]; oacc[nt][1] *= inv[0];
        oacc[nt][2] *= inv[1]; oacc[nt][3] *= inv[1];
    }

    const int bb = g >> 4, hh = g & 15;
    #pragma unroll
    for (int half = 0; half < 2; ++half) {
        int grow = m0 + wm + (l >> 2) + half * 8;
        const float* vr = Vg + (long)grow * HD_;
        float vv[16];
        float dov = 0.0f, dvv = 0.0f;
        #pragma unroll
        for (int nt = 0; nt < 8; ++nt) {
            float2 t = *(const float2*)(vr + nt * 8 + (l & 3) * 2);
            vv[2*nt] = t.x; vv[2*nt+1] = t.y;
            float o0 = oacc[nt][half*2], o1 = oacc[nt][half*2+1];
            dov += o0 * t.x + o1 * t.y;
            dvv += t.x * t.x + t.y * t.y;
        }
        dov += __shfl_xor_sync(0xffffffffu, dov, 1);
        dov += __shfl_xor_sync(0xffffffffu, dov, 2);
        dvv += __shfl_xor_sync(0xffffffffu, dvv, 1);
        dvv += __shfl_xor_sync(0xffffffffu, dvv, 2);
        float al_ = dov / (dvv + 1e-8f);
        float* ob = OB + ((long)(bb * S_ + grow) * D_ + hh * HD_);
        #pragma unroll
        for (int nt = 0; nt < 8; ++nt) {
            float2 r;
            r.x = oacc[nt][half*2]   - al_ * vv[2*nt];
            r.y = oacc[nt][half*2+1] - al_ * vv[2*nt+1];
            *(float2*)(ob + nt * 8 + (l & 3) * 2) = r;
        }
    }
}

// ============================================================================
// GEMM staging: fp32 gmem (K-contiguous rows) -> hi/lo bf16 swizzled smem.
// Tile rows x 32 k-elems; smem row = 64 B; chunk swizzle c ^ ((row>>1)&3).
// ============================================================================
template<int ITEMS>
__device__ __forceinline__ void stage_load(float4 (*pf)[2],
    const float* __restrict__ src, int lds, int kc, int tid)
{
    #pragma unroll
    for (int i = 0; i < ITEMS; ++i) {
        int idx = tid + i * 256;
        int row = idx >> 2, ci = idx & 3;
        const float* p = src + (long)row * lds + kc + ci * 8;
        pf[i][0] = *(const float4*)p;
        pf[i][1] = *(const float4*)(p + 4);
    }
}

template<int ITEMS>
__device__ __forceinline__ void stage_store(float4 (*pf)[2], char* hi, char* lo, int tid)
{
    #pragma unroll
    for (int i = 0; i < ITEMS; ++i) {
        int idx = tid + i * 256;
        int row = idx >> 2, ci = idx & 3;
        float f[8] = { pf[i][0].x, pf[i][0].y, pf[i][0].z, pf[i][0].w,
                       pf[i][1].x, pf[i][1].y, pf[i][1].z, pf[i][1].w };
        uint32_t hw[4], lw[4];
        #pragma unroll
        for (int j = 0; j < 4; ++j) {
            hw[j] = packbf(f[2*j], f[2*j+1]);
            lw[j] = packbf_lo(f[2*j], f[2*j+1], hw[j]);
        }
        uint32_t off = (uint32_t)(row * 64) + (uint32_t)(((ci ^ ((row >> 1) & 3)) << 4));
        *(uint4*)(hi + off) = make_uint4(hw[0], hw[1], hw[2], hw[3]);
        *(uint4*)(lo + off) = make_uint4(lw[0], lw[1], lw[2], lw[3]);
    }
}

// ============================================================================
// HMMA GEMM body: C = A W^T + bias. BM=128, BN=128, BK=32.
// bf16 2-term split. Double-buffered smem + register prefetch.
// MODE 0: flat store. MODE 1: [b,h,s,hd] head store.
// ============================================================================
template<int MODE>
__device__ __forceinline__ void
gemm_body(const float* __restrict__ A, const float* __restrict__ W,
          const float* __restrict__ bias, float* __restrict__ C,
          int K, int lda, int ldw, int ldc, char* smem)
{
    constexpr int ABYTES = 128 * 64;
    constexpr int BBYTES = 128 * 64;
    constexpr int STG    = 2 * ABYTES + 2 * BBYTES;

    const int tid = threadIdx.x;
    const int wid = tid >> 5;
    const int l   = tid & 31;
    const int m0  = blockIdx.y * 128;
    const int n0  = blockIdx.x * 128;
    const int wm  = (wid / 4) * 64;
    const int wn  = (wid % 4) * 32;

    const float* At = A + (long)m0 * lda;
    const float* Wt = W + (long)n0 * ldw;

    const int aRow = (l & 15);
    const int aCk  = (l >> 4);
    const int bRow = ((l >> 4) & 1) * 8 + (l & 7);
    const int bCk  = (l >> 3) & 1;

    int raRow[4], raSwz[4];
    #pragma unroll
    for (int mt = 0; mt < 4; ++mt) {
        raRow[mt] = wm + mt * 16 + aRow;
        raSwz[mt] = (raRow[mt] >> 1) & 3;
    }
    int rbRow[2], rbSwz[2];
    #pragma unroll
    for (int nb = 0; nb < 2; ++nb) {
        rbRow[nb] = wn + nb * 16 + bRow;
        rbSwz[nb] = (rbRow[nb] >> 1) & 3;
    }

    float acc[4][4][4];
    #pragma unroll
    for (int a = 0; a < 4; ++a)
        #pragma unroll
        for (int b = 0; b < 4; ++b)
            #pragma unroll
            for (int c = 0; c < 4; ++c) acc[a][b][c] = 0.0f;

    const uint32_t sb = smem_u32(smem);
    const int nch = K / 32;

    float4 pfA[2][2], pfB[2][2];
    stage_load<2>(pfA, At, lda, 0, tid);
    stage_load<2>(pfB, Wt, ldw, 0, tid);

    for (int c = 0; c < nch; ++c) {
        char* buf = smem + (c & 1) * STG;
        stage_store<2>(pfA, buf,              buf + ABYTES, tid);
        stage_store<2>(pfB, buf + 2*ABYTES,   buf + 2*ABYTES + BBYTES, tid);
        __syncthreads();

        if (c + 1 < nch) {
            stage_load<2>(pfA, At, lda, (c + 1) * 32, tid);
            stage_load<2>(pfB, Wt, ldw, (c + 1) * 32, tid);
        }

        const uint32_t ahi = sb + (c & 1) * STG;
        const uint32_t alo = ahi + ABYTES;
        const uint32_t bhi = alo + ABYTES;
        const uint32_t blo = bhi + BBYTES;

        #pragma unroll
        for (int ks = 0; ks < 2; ++ks) {
            uint32_t ah[4][4], al[4][4], bh[2][4], bl[2][4];
            #pragma unroll
            for (int mt = 0; mt < 4; ++mt) {
                uint32_t off = (uint32_t)(raRow[mt] * 64)
                             + (uint32_t)((((2*ks + aCk) ^ raSwz[mt]) << 4));
                ldm_x4(ah[mt], ahi + off);
                ldm_x4(al[mt], alo + off);
            }
            #pragma unroll
            for (int nb = 0; nb < 2; ++nb) {
                uint32_t off = (uint32_t)(rbRow[nb] * 64)
                             + (uint32_t)((((2*ks + bCk) ^ rbSwz[nb]) << 4));
                ldm_x4(bh[nb], bhi + off);
                ldm_x4(bl[nb], blo + off);
            }
            #pragma unroll
            for (int mt = 0; mt < 4; ++mt) {
                #pragma unroll
                for (int nt = 0; nt < 4; ++nt) {
                    const uint32_t* pbh = &bh[nt >> 1][(nt & 1) * 2];
                    const uint32_t* pbl = &bl[nt >> 1][(nt & 1) * 2];
                    mma16816(acc[mt][nt], ah[mt], pbh[0], pbh[1]);
                    mma16816(acc[mt][nt], ah[mt], pbl[0], pbl[1]);
                    mma16816(acc[mt][nt], al[mt], pbh[0], pbh[1]);
                }
            }
        }
        __syncthreads();
    }

    #pragma unroll
    for (int mt = 0; mt < 4; ++mt) {
        #pragma unroll
        for (int nt = 0; nt < 4; ++nt) {
            int n = n0 + wn + nt * 8 + (l & 3) * 2;
            float2 bb = *(const float2*)(bias + n);
            #pragma unroll
            for (int half = 0; half < 2; ++half) {
                int m = m0 + wm + mt * 16 + (l >> 2) + half * 8;
                float2 r;
                r.x = acc[mt][nt][half*2]   + bb.x;
                r.y = acc[mt][nt][half*2+1] + bb.y;
                if (MODE == 0) {
                    *(float2*)(C + (long)m * ldc + n) = r;
                } else {
                    int b2 = m >> 11, s = m & 2047;
                    int h = n >> 6, hd = n & 63;
                    *(float2*)(C + (((long)(b2 * H_ + h) * S_ + s) * HD_ + hd)) = r;
                }
            }
        }
    }
}

// output projection
__global__ void __launch_bounds__(256, 1)
gemm_out(const float* __restrict__ A, const float* __restrict__ W,
         const float* __restrict__ bias, float* __restrict__ C)
{
    extern __shared__ char smem[];
    gemm_body<0>(A, W, bias, C, D_, D_, D_, D_, smem);
}

// merged Q/K/V projections: blockIdx.z selects weight/bias/output
__global__ void __launch_bounds__(256, 1)
gemm_qkv(const float* __restrict__ x,
         const float* __restrict__ wq, const float* __restrict__ bq,
         const float* __restrict__ wk, const float* __restrict__ bk,
         const float* __restrict__ wv, const float* __restrict__ bv,
         float* __restrict__ q, float* __restrict__ k, float* __restrict__ v)
{
    extern __shared__ char smem[];
    const int z = blockIdx.z;
    const float* W = (z == 0) ? wq : (z == 1) ? wk : wv;
    const float* bias = (z == 0) ? bq : (z == 1) ? bk : bv;
    float* C = (z == 0) ? q : (z == 1) ? k : v;
    gemm_body<1>(x, W, bias, C, D_, D_, D_, 0, smem);
}

// ============================================================================
extern "C" void kernel_launch(void* const* d_in, const int* in_sizes, int n_in,
                              void* d_out, int out_size)
{
    const float* x  = (const float*)d_in[0];
    const float* wq = (const float*)d_in[1];
    const float* bq = (const float*)d_in[2];
    const float* wk = (const float*)d_in[3];
    const float* bk = (const float*)d_in[4];
    const float* wv = (const float*)d_in[5];
    const float* bv = (const float*)d_in[6];
    const float* wo = (const float*)d_in[7];
    const float* bo = (const float*)d_in[8];
    float* out = (float*)d_out;

    float *q, *k, *v, *ob;
    cudaGetSymbolAddress((void**)&q,  g_q);
    cudaGetSymbolAddress((void**)&k,  g_k);
    cudaGetSymbolAddress((void**)&v,  g_v);
    cudaGetSymbolAddress((void**)&ob, g_ob);

    const int SMG = 2 * (2*128*64 + 2*128*64);   // 65536
    const int SMF = 163840;                       // Q 32K + K 64K + V 64K
    cudaFuncSetAttribute(gemm_qkv,  cudaFuncAttributeMaxDynamicSharedMemorySize, SMG);
    cudaFuncSetAttribute(gemm_out,  cudaFuncAttributeMaxDynamicSharedMemorySize, SMG);
    cudaFuncSetAttribute(fused_attn, cudaFuncAttributeMaxDynamicSharedMemorySize, SMF);

    // 1) Q/K/V projections (one launch) -> head layout [b,h,s,hd]
    gemm_qkv<<<dim3(D_/128, M_/128, 3), 256, SMG>>>(
        x, wq, bq, wk, bk, wv, bv, q, k, v);

    // 2) fused attention + softmax + exclusion -> ob [b,s,d]
    fused_attn<<<dim3(S_/128, G_), 256, SMF>>>(q, k, v, ob);

    // 3) output projection -> d_out
    gemm_out<<<dim3(D_/128, M_/128, 1), 256, SMG>>>(ob, wo, bo, out);
}

// round 8
// speedup vs baseline: 3.3657x; 1.2284x over previous
#include <cuda_runtime.h>
#include <cuda_bf16.h>
#include <cstdint>

#define B_   2
#define S_   2048
#define D_   1024
#define H_   16
#define HD_  64
#define M_   (B_*S_)     // 4096
#define G_   (B_*H_)     // 32
#define NE_  ((size_t)M_*D_)   // 4194304

// ---- scratch (static device arrays; no allocation allowed) ----
__device__ __nv_bfloat16 g_xh[NE_], g_xl[NE_];      // x bf16 hi/lo
__device__ __nv_bfloat16 g_wh[NE_], g_wl[NE_];      // wq|wk|wv|wo hi/lo
__device__ __nv_bfloat16 g_qh[NE_], g_ql[NE_];      // Q head layout [g,s,hd]
__device__ __nv_bfloat16 g_kh[NE_], g_kl[NE_];
__device__ __nv_bfloat16 g_vh[NE_], g_vl[NE_];
__device__ float         g_vf[NE_];                 // V fp32 (exclusion)
__device__ __nv_bfloat16 g_obh[NE_], g_obl[NE_];    // attn out [b,s,d]

// ============================================================================
// helpers
// ============================================================================
__device__ __forceinline__ uint32_t smem_u32(const void* p) {
    uint32_t a;
    asm("{ .reg .u64 t; cvta.to.shared.u64 t, %1; cvt.u32.u64 %0, t; }"
        : "=r"(a) : "l"(p));
    return a;
}
__device__ __forceinline__ void ldm_x4(uint32_t* r, uint32_t addr) {
    asm volatile("ldmatrix.sync.aligned.m8n8.x4.shared.b16 {%0,%1,%2,%3}, [%4];"
        : "=r"(r[0]), "=r"(r[1]), "=r"(r[2]), "=r"(r[3]) : "r"(addr));
}
__device__ __forceinline__ void ldm_x4_t(uint32_t* r, uint32_t addr) {
    asm volatile("ldmatrix.sync.aligned.m8n8.x4.trans.shared.b16 {%0,%1,%2,%3}, [%4];"
        : "=r"(r[0]), "=r"(r[1]), "=r"(r[2]), "=r"(r[3]) : "r"(addr));
}
__device__ __forceinline__ void mma16816(float* c, const uint32_t* a,
                                         uint32_t b0, uint32_t b1) {
    asm volatile(
        "mma.sync.aligned.m16n8k16.row.col.f32.bf16.bf16.f32 "
        "{%0,%1,%2,%3}, {%4,%5,%6,%7}, {%8,%9}, {%0,%1,%2,%3};"
        : "+f"(c[0]), "+f"(c[1]), "+f"(c[2]), "+f"(c[3])
        : "r"(a[0]), "r"(a[1]), "r"(a[2]), "r"(a[3]), "r"(b0), "r"(b1));
}
__device__ __forceinline__ uint32_t packbf(float x, float y) {
    __nv_bfloat162 t;
    t.x = __float2bfloat16_rn(x);
    t.y = __float2bfloat16_rn(y);
    return *(uint32_t*)&t;
}
__device__ __forceinline__ uint32_t packbf_lo(float x, float y, uint32_t hi) {
    __nv_bfloat162 h = *(__nv_bfloat162*)&hi;
    return packbf(x - __bfloat162float(h.x), y - __bfloat162float(h.y));
}
__device__ __forceinline__ void cpa(uint32_t dst, const void* src) {
    asm volatile("cp.async.cg.shared.global [%0], [%1], 16;"
        :: "r"(dst), "l"(src) : "memory");
}
#define CP_COMMIT() asm volatile("cp.async.commit_group;" ::: "memory")
#define CP_WAIT(n)  asm volatile("cp.async.wait_group %0;" :: "n"(n) : "memory")

// ============================================================================
// Convert pass: x (4 quarters) + 4 weights -> bf16 hi/lo
// grid (512, 8), 256 threads; each thread 8 elems
// ============================================================================
__global__ void __launch_bounds__(256)
convert_all(const float* __restrict__ x,
            const float* __restrict__ wq, const float* __restrict__ wk,
            const float* __restrict__ wv, const float* __restrict__ wo,
            __nv_bfloat16* __restrict__ xh, __nv_bfloat16* __restrict__ xl,
            __nv_bfloat16* __restrict__ wh, __nv_bfloat16* __restrict__ wl)
{
    const int z = blockIdx.y;
    const float* src;
    __nv_bfloat16 *dh, *dl;
    if (z < 4) {
        src = x  + ((long)z << 20);
        dh  = xh + ((long)z << 20);
        dl  = xl + ((long)z << 20);
    } else {
        const float* ws = (z == 4) ? wq : (z == 5) ? wk : (z == 6) ? wv : wo;
        src = ws;
        dh  = wh + ((long)(z - 4) << 20);
        dl  = wl + ((long)(z - 4) << 20);
    }
    long i = ((long)blockIdx.x * 256 + threadIdx.x) * 8;
    float4 a = *(const float4*)(src + i);
    float4 b = *(const float4*)(src + i + 4);
    uint32_t h0 = packbf(a.x, a.y), h1 = packbf(a.z, a.w);
    uint32_t h2 = packbf(b.x, b.y), h3 = packbf(b.z, b.w);
    uint32_t l0 = packbf_lo(a.x, a.y, h0), l1 = packbf_lo(a.z, a.w, h1);
    uint32_t l2 = packbf_lo(b.x, b.y, h2), l3 = packbf_lo(b.z, b.w, h3);
    *(uint4*)(dh + i) = make_uint4(h0, h1, h2, h3);
    *(uint4*)(dl + i) = make_uint4(l0, l1, l2, l3);
}

// ============================================================================
// bf16 cp.async GEMM: C = A W^T (+bias). BM=BN=128, BK=32, 3-stage pipeline.
// A,W bf16 hi/lo row-major [.,1024]. Stage = A hi/lo 16K + B hi/lo 16K = 32KB.
// smem row 64B, chunk swizzle ch ^ ((row>>1)&3).
// MODE 0: fp32 flat store. MODE 1: bf16 hi/lo head store (+opt fp32 head).
// ============================================================================
__device__ __forceinline__ void gemm_issue(
    const __nv_bfloat16* __restrict__ Ah, const __nv_bfloat16* __restrict__ Al,
    const __nv_bfloat16* __restrict__ Wh, const __nv_bfloat16* __restrict__ Wl,
    int m0, int n0, int s, uint32_t sb, int tid)
{
    const int kc = s * 32;
    const uint32_t stb = sb + (uint32_t)((s % 3) * 32768);
    #pragma unroll
    for (int it = 0; it < 8; ++it) {
        int idx  = tid + it * 256;
        int bsel = idx >> 9;
        int ci   = idx & 511;
        int row  = ci >> 2, ch = ci & 3;
        const __nv_bfloat16* src =
            (bsel == 0) ? Ah + (long)(m0 + row) * 1024 + kc + ch * 8 :
            (bsel == 1) ? Al + (long)(m0 + row) * 1024 + kc + ch * 8 :
            (bsel == 2) ? Wh + (long)(n0 + row) * 1024 + kc + ch * 8 :
                          Wl + (long)(n0 + row) * 1024 + kc + ch * 8;
        uint32_t dst = stb + (uint32_t)(bsel * 8192) + (uint32_t)(row * 64)
                     + (uint32_t)(((ch ^ ((row >> 1) & 3)) << 4));
        cpa(dst, src);
    }
}

template<int MODE>
__device__ __forceinline__ void gemm_async(
    const __nv_bfloat16* __restrict__ Ah, const __nv_bfloat16* __restrict__ Al,
    const __nv_bfloat16* __restrict__ Wh, const __nv_bfloat16* __restrict__ Wl,
    const float* __restrict__ bias,
    float* __restrict__ Cf,
    __nv_bfloat16* __restrict__ Oh, __nv_bfloat16* __restrict__ Ol,
    float* __restrict__ Of,
    char* smem)
{
    const int tid = threadIdx.x;
    const int wid = tid >> 5;
    const int l   = tid & 31;
    const int m0  = blockIdx.y * 128;
    const int n0  = blockIdx.x * 128;
    const int wm  = (wid / 4) * 64;
    const int wn  = (wid % 4) * 32;

    const int aRow = (l & 15);
    const int aCk  = (l >> 4);
    const int bRow = ((l >> 4) & 1) * 8 + (l & 7);
    const int bCk  = (l >> 3) & 1;

    float acc[4][4][4];
    #pragma unroll
    for (int a = 0; a < 4; ++a)
        #pragma unroll
        for (int b = 0; b < 4; ++b)
            #pragma unroll
            for (int c = 0; c < 4; ++c) acc[a][b][c] = 0.0f;

    const uint32_t sb = smem_u32(smem);

    gemm_issue(Ah, Al, Wh, Wl, m0, n0, 0, sb, tid); CP_COMMIT();
    gemm_issue(Ah, Al, Wh, Wl, m0, n0, 1, sb, tid); CP_COMMIT();

    for (int c = 0; c < 32; ++c) {
        __syncthreads();              // all warps done with buffer (c+2)%3
        if (c + 2 < 32) {
            gemm_issue(Ah, Al, Wh, Wl, m0, n0, c + 2, sb, tid);
            CP_COMMIT();
            CP_WAIT(2);
        } else if (c == 30) {
            CP_WAIT(1);
        } else {
            CP_WAIT(0);
        }
        __syncthreads();

        const uint32_t ahi = sb + (uint32_t)((c % 3) * 32768);
        const uint32_t alo = ahi + 8192;
        const uint32_t bhi = ahi + 16384;
        const uint32_t blo = ahi + 24576;

        #pragma unroll
        for (int ks = 0; ks < 2; ++ks) {
            uint32_t ah[4][4], al[4][4], bh[2][4], bl[2][4];
            #pragma unroll
            for (int mt = 0; mt < 4; ++mt) {
                int row = wm + mt * 16 + aRow;
                uint32_t off = (uint32_t)(row * 64)
                             + (uint32_t)((((2*ks + aCk) ^ ((row >> 1) & 3)) << 4));
                ldm_x4(ah[mt], ahi + off);
                ldm_x4(al[mt], alo + off);
            }
            #pragma unroll
            for (int nb = 0; nb < 2; ++nb) {
                int row = wn + nb * 16 + bRow;
                uint32_t off = (uint32_t)(row * 64)
                             + (uint32_t)((((2*ks + bCk) ^ ((row >> 1) & 3)) << 4));
                ldm_x4(bh[nb], bhi + off);
                ldm_x4(bl[nb], blo + off);
            }
            #pragma unroll
            for (int mt = 0; mt < 4; ++mt) {
                #pragma unroll
                for (int nt = 0; nt < 4; ++nt) {
                    const uint32_t* pbh = &bh[nt >> 1][(nt & 1) * 2];
                    const uint32_t* pbl = &bl[nt >> 1][(nt & 1) * 2];
                    mma16816(acc[mt][nt], ah[mt], pbh[0], pbh[1]);
                    mma16816(acc[mt][nt], ah[mt], pbl[0], pbl[1]);
                    mma16816(acc[mt][nt], al[mt], pbh[0], pbh[1]);
                }
            }
        }
    }

    #pragma unroll
    for (int mt = 0; mt < 4; ++mt) {
        #pragma unroll
        for (int nt = 0; nt < 4; ++nt) {
            int n = n0 + wn + nt * 8 + (l & 3) * 2;
            float2 bb = *(const float2*)(bias + n);
            #pragma unroll
            for (int half = 0; half < 2; ++half) {
                int m = m0 + wm + mt * 16 + (l >> 2) + half * 8;
                float2 r;
                r.x = acc[mt][nt][half*2]   + bb.x;
                r.y = acc[mt][nt][half*2+1] + bb.y;
                if (MODE == 0) {
                    *(float2*)(Cf + (long)m * 1024 + n) = r;
                } else {
                    int b2 = m >> 11, s = m & 2047;
                    int h = n >> 6, hd = n & 63;
                    long addr = ((long)(b2 * H_ + h) * S_ + s) * HD_ + hd;
                    uint32_t hv = packbf(r.x, r.y);
                    *(uint32_t*)(Oh + addr) = hv;
                    *(uint32_t*)(Ol + addr) = packbf_lo(r.x, r.y, hv);
                    if (Of) *(float2*)(Of + addr) = r;
                }
            }
        }
    }
}

__global__ void __launch_bounds__(256, 2)
gemm_qkv(const __nv_bfloat16* __restrict__ xh, const __nv_bfloat16* __restrict__ xl,
         const __nv_bfloat16* __restrict__ wh, const __nv_bfloat16* __restrict__ wl,
         const float* __restrict__ bq, const float* __restrict__ bk,
         const float* __restrict__ bv,
         __nv_bfloat16* __restrict__ qh, __nv_bfloat16* __restrict__ ql,
         __nv_bfloat16* __restrict__ kh, __nv_bfloat16* __restrict__ kl,
         __nv_bfloat16* __restrict__ vh, __nv_bfloat16* __restrict__ vl,
         float* __restrict__ vf)
{
    extern __shared__ char smem[];
    const int z = blockIdx.z;
    const __nv_bfloat16* Wh = wh + ((long)z << 20);
    const __nv_bfloat16* Wl = wl + ((long)z << 20);
    const float* bias = (z == 0) ? bq : (z == 1) ? bk : bv;
    __nv_bfloat16* Oh = (z == 0) ? qh : (z == 1) ? kh : vh;
    __nv_bfloat16* Ol = (z == 0) ? ql : (z == 1) ? kl : vl;
    float* Of = (z == 2) ? vf : nullptr;
    gemm_async<1>(xh, xl, Wh, Wl, bias, nullptr, Oh, Ol, Of, smem);
}

__global__ void __launch_bounds__(256, 2)
gemm_out(const __nv_bfloat16* __restrict__ ah, const __nv_bfloat16* __restrict__ al,
         const __nv_bfloat16* __restrict__ wh, const __nv_bfloat16* __restrict__ wl,
         const float* __restrict__ bias, float* __restrict__ C)
{
    extern __shared__ char smem[];
    gemm_async<0>(ah, al, wh + ((long)3 << 20), wl + ((long)3 << 20),
                  bias, C, nullptr, nullptr, nullptr, smem);
}

// ============================================================================
// Fused attention with cp.async K/V double-buffering.
// Grid (S/128, G). smem: Q hi/lo 32K | K x2 64K | V x2 64K = 160 KB.
// Tile smem image: 128 rows x 128B, chunk swizzle ch ^ (row&7).
// ============================================================================
__device__ __forceinline__ void issue_tile(const __nv_bfloat16* __restrict__ Gh,
    const __nv_bfloat16* __restrict__ Gl, uint32_t dst_hi, int tid)
{
    #pragma unroll
    for (int it = 0; it < 4; ++it) {
        int idx = tid + it * 256;
        int row = idx >> 3, ch = idx & 7;
        uint32_t off = (uint32_t)(row * 128) + (uint32_t)(((ch ^ (row & 7)) << 4));
        cpa(dst_hi + off,         Gh + row * 64 + ch * 8);
        cpa(dst_hi + 16384 + off, Gl + row * 64 + ch * 8);
    }
}

__global__ void __launch_bounds__(256, 1)
fused_attn(const __nv_bfloat16* __restrict__ Qh, const __nv_bfloat16* __restrict__ Ql,
           const __nv_bfloat16* __restrict__ Kh, const __nv_bfloat16* __restrict__ Kl,
           const __nv_bfloat16* __restrict__ Vh, const __nv_bfloat16* __restrict__ Vl,
           const float* __restrict__ VF,
           __nv_bfloat16* __restrict__ OBh, __nv_bfloat16* __restrict__ OBl)
{
    extern __shared__ char sm[];
    const int tid = threadIdx.x;
    const int wid = tid >> 5;
    const int l   = tid & 31;
    const int g   = blockIdx.y;
    const int m0  = blockIdx.x * 128;
    const int wm  = wid * 16;

    const long gbase = (long)g * S_ * HD_;
    const __nv_bfloat16* Qgh = Qh + gbase + (long)m0 * HD_;
    const __nv_bfloat16* Qgl = Ql + gbase + (long)m0 * HD_;
    const __nv_bfloat16* Kgh = Kh + gbase;
    const __nv_bfloat16* Kgl = Kl + gbase;
    const __nv_bfloat16* Vgh = Vh + gbase;
    const __nv_bfloat16* Vgl = Vl + gbase;

    const uint32_t sb = smem_u32(sm);
    const uint32_t qb = sb;

    // prologue: Q + K0 + V0 in group 0
    issue_tile(Qgh, Qgl, sb, tid);
    issue_tile(Kgh, Kgl, sb + 32768, tid);
    issue_tile(Vgh, Vgl, sb + 98304, tid);
    CP_COMMIT();

    float oacc[8][4];
    #pragma unroll
    for (int i = 0; i < 8; ++i)
        #pragma unroll
        for (int j = 0; j < 4; ++j) oacc[i][j] = 0.0f;
    float mrun[2] = {-1e30f, -1e30f};
    float lsum[2] = {0.0f, 0.0f};

    const int aR = wm + (l & 15);
    const int bR = ((l >> 4) & 1) * 8 + (l & 7);
    const int bC = (l >> 3) & 1;
    const int vR = (l & 15);
    const int vC = (l >> 4);

    for (int j = 0; j < 16; ++j) {
        const int cur = j & 1;
        const uint32_t kb = sb + 32768 + cur * 32768;
        const uint32_t vb = sb + 98304 + cur * 32768;

        __syncthreads();   // buffer (j+1)&1 free (consumed in iter j-1)
        if (j + 1 < 16) {
            const int nxt = cur ^ 1;
            issue_tile(Kgh + (long)(j + 1) * 8192, Kgl + (long)(j + 1) * 8192,
                       sb + 32768 + nxt * 32768, tid);
            issue_tile(Vgh + (long)(j + 1) * 8192, Vgl + (long)(j + 1) * 8192,
                       sb + 98304 + nxt * 32768, tid);
            CP_COMMIT();
        }
        if (j < 15) { CP_WAIT(1); } else { CP_WAIT(0); }
        __syncthreads();

        // ---- S = Q K^T : warp tile 16 x 128 ----
        float sacc[16][4];
        #pragma unroll
        for (int i = 0; i < 16; ++i)
            #pragma unroll
            for (int c = 0; c < 4; ++c) sacc[i][c] = 0.0f;

        #pragma unroll
        for (int ks = 0; ks < 4; ++ks) {
            uint32_t ah[4], al[4];
            {
                uint32_t off = (uint32_t)(aR * 128)
                             + (uint32_t)((((ks * 2 + (l >> 4)) ^ (aR & 7)) << 4));
                ldm_x4(ah, qb + off);
                ldm_x4(al, qb + 16384 + off);
            }
            #pragma unroll
            for (int nb = 0; nb < 8; ++nb) {
                uint32_t bh[4], bl[4];
                int row = nb * 16 + bR;
                uint32_t off = (uint32_t)(row * 128)
                             + (uint32_t)((((ks * 2 + bC) ^ (row & 7)) << 4));
                ldm_x4(bh, kb + off);
                ldm_x4(bl, kb + 16384 + off);
                #pragma unroll
                for (int nt2 = 0; nt2 < 2; ++nt2) {
                    float* c = sacc[nb * 2 + nt2];
                    mma16816(c, ah, bh[nt2*2], bh[nt2*2+1]);
                    mma16816(c, ah, bl[nt2*2], bl[nt2*2+1]);
                    mma16816(c, al, bh[nt2*2], bh[nt2*2+1]);
                }
            }
        }

        // ---- online softmax ----
        float mnew[2] = {-1e30f, -1e30f};
        #pragma unroll
        for (int nt = 0; nt < 16; ++nt) {
            #pragma unroll
            for (int c = 0; c < 4; ++c) sacc[nt][c] *= 0.125f;
            mnew[0] = fmaxf(mnew[0], fmaxf(sacc[nt][0], sacc[nt][1]));
            mnew[1] = fmaxf(mnew[1], fmaxf(sacc[nt][2], sacc[nt][3]));
        }
        #pragma unroll
        for (int h = 0; h < 2; ++h) {
            mnew[h] = fmaxf(mnew[h], __shfl_xor_sync(0xffffffffu, mnew[h], 1));
            mnew[h] = fmaxf(mnew[h], __shfl_xor_sync(0xffffffffu, mnew[h], 2));
        }
        float corr[2];
        #pragma unroll
        for (int h = 0; h < 2; ++h) {
            float mi = fmaxf(mrun[h], mnew[h]);
            corr[h] = __expf(mrun[h] - mi);
            mrun[h] = mi;
            lsum[h] *= corr[h];
        }
        float rs[2] = {0.0f, 0.0f};
        #pragma unroll
        for (int nt = 0; nt < 16; ++nt) {
            sacc[nt][0] = __expf(sacc[nt][0] - mrun[0]);
            sacc[nt][1] = __expf(sacc[nt][1] - mrun[0]);
            sacc[nt][2] = __expf(sacc[nt][2] - mrun[1]);
            sacc[nt][3] = __expf(sacc[nt][3] - mrun[1]);
            rs[0] += sacc[nt][0] + sacc[nt][1];
            rs[1] += sacc[nt][2] + sacc[nt][3];
        }
        #pragma unroll
        for (int h = 0; h < 2; ++h) {
            rs[h] += __shfl_xor_sync(0xffffffffu, rs[h], 1);
            rs[h] += __shfl_xor_sync(0xffffffffu, rs[h], 2);
            lsum[h] += rs[h];
        }
        #pragma unroll
        for (int nt = 0; nt < 8; ++nt) {
            oacc[nt][0] *= corr[0]; oacc[nt][1] *= corr[0];
            oacc[nt][2] *= corr[1]; oacc[nt][3] *= corr[1];
        }

        // ---- O += P V ----
        #pragma unroll
        for (int kt = 0; kt < 8; ++kt) {
            uint32_t ph[4], pl[4];
            ph[0] = packbf(sacc[2*kt][0],   sacc[2*kt][1]);
            ph[1] = packbf(sacc[2*kt][2],   sacc[2*kt][3]);
            ph[2] = packbf(sacc[2*kt+1][0], sacc[2*kt+1][1]);
            ph[3] = packbf(sacc[2*kt+1][2], sacc[2*kt+1][3]);
            pl[0] = packbf_lo(sacc[2*kt][0],   sacc[2*kt][1],   ph[0]);
            pl[1] = packbf_lo(sacc[2*kt][2],   sacc[2*kt][3],   ph[1]);
            pl[2] = packbf_lo(sacc[2*kt+1][0], sacc[2*kt+1][1], ph[2]);
            pl[3] = packbf_lo(sacc[2*kt+1][2], sacc[2*kt+1][3], ph[3]);
            #pragma unroll
            for (int np = 0; np < 4; ++np) {
                uint32_t vh[4], vl[4];
                int row = kt * 16 + vR;
                uint32_t off = (uint32_t)(row * 128)
                             + (uint32_t)((((np * 2 + vC) ^ (row & 7)) << 4));
                ldm_x4_t(vh, vb + off);
                ldm_x4_t(vl, vb + 16384 + off);
                #pragma unroll
                for (int d2 = 0; d2 < 2; ++d2) {
                    float* c = oacc[np * 2 + d2];
                    mma16816(c, ph, vh[d2*2], vh[d2*2+1]);
                    mma16816(c, ph, vl[d2*2], vl[d2*2+1]);
                    mma16816(c, pl, vh[d2*2], vh[d2*2+1]);
                }
            }
        }
    }

    // ---- finalize: 1/l, Gram-Schmidt exclusion, bf16 hi/lo store [b,s,d] ----
    float inv[2] = {1.0f / lsum[0], 1.0f / lsum[1]};
    #pragma unroll
    for (int nt = 0; nt < 8; ++nt) {
        oacc[nt][0] *= inv[0]; oacc[nt][1] *= inv[0];
        oacc[nt][2] *= inv[1]; oacc[nt][3] *= inv[1];
    }

    const int bb = g >> 4, hh = g & 15;
    #pragma unroll
    for (int half = 0; half < 2; ++half) {
        int grow = m0 + wm + (l >> 2) + half * 8;
        const float* vr = VF + gbase + (long)grow * HD_;
        float vv[16];
        float dov = 0.0f, dvv = 0.0f;
        #pragma unroll
        for (int nt = 0; nt < 8; ++nt) {
            float2 t = *(const float2*)(vr + nt * 8 + (l & 3) * 2);
            vv[2*nt] = t.x; vv[2*nt+1] = t.y;
            float o0 = oacc[nt][half*2], o1 = oacc[nt][half*2+1];
            dov += o0 * t.x + o1 * t.y;
            dvv += t.x * t.x + t.y * t.y;
        }
        dov += __shfl_xor_sync(0xffffffffu, dov, 1);
        dov += __shfl_xor_sync(0xffffffffu, dov, 2);
        dvv += __shfl_xor_sync(0xffffffffu, dvv, 1);
        dvv += __shfl_xor_sync(0xffffffffu, dvv, 2);
        float al_ = dov / (dvv + 1e-8f);
        long obase = (long)(bb * S_ + grow) * D_ + hh * HD_;
        #pragma unroll
        for (int nt = 0; nt < 8; ++nt) {
            float rx = oacc[nt][half*2]   - al_ * vv[2*nt];
            float ry = oacc[nt][half*2+1] - al_ * vv[2*nt+1];
            long a = obase + nt * 8 + (l & 3) * 2;
            uint32_t hv = packbf(rx, ry);
            *(uint32_t*)(OBh + a) = hv;
            *(uint32_t*)(OBl + a) = packbf_lo(rx, ry, hv);
        }
    }
}

// ============================================================================
extern "C" void kernel_launch(void* const* d_in, const int* in_sizes, int n_in,
                              void* d_out, int out_size)
{
    const float* x  = (const float*)d_in[0];
    const float* wq = (const float*)d_in[1];
    const float* bq = (const float*)d_in[2];
    const float* wk = (const float*)d_in[3];
    const float* bk = (const float*)d_in[4];
    const float* wv = (const float*)d_in[5];
    const float* bv = (const float*)d_in[6];
    const float* wo = (const float*)d_in[7];
    const float* bo = (const float*)d_in[8];
    float* out = (float*)d_out;

    __nv_bfloat16 *xh, *xl, *wh, *wl, *qh, *ql, *kh, *kl, *vh, *vl, *obh, *obl;
    float *vf;
    cudaGetSymbolAddress((void**)&xh,  g_xh);
    cudaGetSymbolAddress((void**)&xl,  g_xl);
    cudaGetSymbolAddress((void**)&wh,  g_wh);
    cudaGetSymbolAddress((void**)&wl,  g_wl);
    cudaGetSymbolAddress((void**)&qh,  g_qh);
    cudaGetSymbolAddress((void**)&ql,  g_ql);
    cudaGetSymbolAddress((void**)&kh,  g_kh);
    cudaGetSymbolAddress((void**)&kl,  g_kl);
    cudaGetSymbolAddress((void**)&vh,  g_vh);
    cudaGetSymbolAddress((void**)&vl,  g_vl);
    cudaGetSymbolAddress((void**)&vf,  g_vf);
    cudaGetSymbolAddress((void**)&obh, g_obh);
    cudaGetSymbolAddress((void**)&obl, g_obl);

    const int SMG = 3 * 32768;     // 98304
    const int SMF = 163840;
    cudaFuncSetAttribute(gemm_qkv,  cudaFuncAttributeMaxDynamicSharedMemorySize, SMG);
    cudaFuncSetAttribute(gemm_out,  cudaFuncAttributeMaxDynamicSharedMemorySize, SMG);
    cudaFuncSetAttribute(fused_attn, cudaFuncAttributeMaxDynamicSharedMemorySize, SMF);

    // 0) convert x + weights to bf16 hi/lo
    convert_all<<<dim3(512, 8), 256>>>(x, wq, wk, wv, wo, xh, xl, wh, wl);

    // 1) Q/K/V projections -> bf16 hi/lo head layout (+ V fp32)
    gemm_qkv<<<dim3(D_/128, M_/128, 3), 256, SMG>>>(
        xh, xl, wh, wl, bq, bk, bv, qh, ql, kh, kl, vh, vl, vf);

    // 2) fused attention + softmax + exclusion -> ob bf16 hi/lo [b,s,d]
    fused_attn<<<dim3(S_/128, G_), 256, SMF>>>(
        qh, ql, kh, kl, vh, vl, vf, obh, obl);

    // 3) output projection -> d_out
    gemm_out<<<dim3(D_/128, M_/128, 1), 256, SMG>>>(obh, obl, wh, wl, bo, out);
}

// round 9
// speedup vs baseline: 3.3974x; 1.0094x over previous
#include <cuda_runtime.h>
#include <cuda_bf16.h>
#include <cstdint>

#define B_   2
#define S_   2048
#define D_   1024
#define H_   16
#define HD_  64
#define M_   (B_*S_)     // 4096
#define G_   (B_*H_)     // 32
#define NE_  ((size_t)M_*D_)   // 4194304

// ---- scratch (static device arrays; no allocation allowed) ----
__device__ __nv_bfloat16 g_xh[NE_], g_xl[NE_];      // x bf16 hi/lo
__device__ __nv_bfloat16 g_wh[NE_], g_wl[NE_];      // wq|wk|wv|wo hi/lo
__device__ __nv_bfloat16 g_qh[NE_], g_ql[NE_];      // Q head layout [g,s,hd]
__device__ __nv_bfloat16 g_kh[NE_], g_kl[NE_];
__device__ __nv_bfloat16 g_vh[NE_], g_vl[NE_];
__device__ float         g_vf[NE_];                 // V fp32 (exclusion)
__device__ __nv_bfloat16 g_obh[NE_], g_obl[NE_];    // attn out [b,s,d]

// ============================================================================
// helpers
// ============================================================================
__device__ __forceinline__ uint32_t smem_u32(const void* p) {
    uint32_t a;
    asm("{ .reg .u64 t; cvta.to.shared.u64 t, %1; cvt.u32.u64 %0, t; }"
        : "=r"(a) : "l"(p));
    return a;
}
__device__ __forceinline__ void ldm_x4(uint32_t* r, uint32_t addr) {
    asm volatile("ldmatrix.sync.aligned.m8n8.x4.shared.b16 {%0,%1,%2,%3}, [%4];"
        : "=r"(r[0]), "=r"(r[1]), "=r"(r[2]), "=r"(r[3]) : "r"(addr));
}
__device__ __forceinline__ void ldm_x4_t(uint32_t* r, uint32_t addr) {
    asm volatile("ldmatrix.sync.aligned.m8n8.x4.trans.shared.b16 {%0,%1,%2,%3}, [%4];"
        : "=r"(r[0]), "=r"(r[1]), "=r"(r[2]), "=r"(r[3]) : "r"(addr));
}
__device__ __forceinline__ void mma16816(float* c, const uint32_t* a,
                                         uint32_t b0, uint32_t b1) {
    asm volatile(
        "mma.sync.aligned.m16n8k16.row.col.f32.bf16.bf16.f32 "
        "{%0,%1,%2,%3}, {%4,%5,%6,%7}, {%8,%9}, {%0,%1,%2,%3};"
        : "+f"(c[0]), "+f"(c[1]), "+f"(c[2]), "+f"(c[3])
        : "r"(a[0]), "r"(a[1]), "r"(a[2]), "r"(a[3]), "r"(b0), "r"(b1));
}
__device__ __forceinline__ uint32_t packbf(float x, float y) {
    __nv_bfloat162 t;
    t.x = __float2bfloat16_rn(x);
    t.y = __float2bfloat16_rn(y);
    return *(uint32_t*)&t;
}
__device__ __forceinline__ uint32_t packbf_lo(float x, float y, uint32_t hi) {
    __nv_bfloat162 h = *(__nv_bfloat162*)&hi;
    return packbf(x - __bfloat162float(h.x), y - __bfloat162float(h.y));
}
__device__ __forceinline__ float fexp2(float x) {
    float y;
    asm("ex2.approx.f32 %0, %1;" : "=f"(y) : "f"(x));
    return y;
}
__device__ __forceinline__ void cpa(uint32_t dst, const void* src) {
    asm volatile("cp.async.cg.shared.global [%0], [%1], 16;"
        :: "r"(dst), "l"(src) : "memory");
}
#define CP_COMMIT() asm volatile("cp.async.commit_group;" ::: "memory")
#define CP_WAIT(n)  asm volatile("cp.async.wait_group %0;" :: "n"(n) : "memory")

// 0.125 (1/sqrt(64)) * log2(e)  -> softmax run in log2 domain
#define SSCALE 0.18033688f

// ============================================================================
// Convert pass: x (4 quarters) + 4 weights -> bf16 hi/lo
// ============================================================================
__global__ void __launch_bounds__(256)
convert_all(const float* __restrict__ x,
            const float* __restrict__ wq, const float* __restrict__ wk,
            const float* __restrict__ wv, const float* __restrict__ wo,
            __nv_bfloat16* __restrict__ xh, __nv_bfloat16* __restrict__ xl,
            __nv_bfloat16* __restrict__ wh, __nv_bfloat16* __restrict__ wl)
{
    const int z = blockIdx.y;
    const float* src;
    __nv_bfloat16 *dh, *dl;
    if (z < 4) {
        src = x  + ((long)z << 20);
        dh  = xh + ((long)z << 20);
        dl  = xl + ((long)z << 20);
    } else {
        const float* ws = (z == 4) ? wq : (z == 5) ? wk : (z == 6) ? wv : wo;
        src = ws;
        dh  = wh + ((long)(z - 4) << 20);
        dl  = wl + ((long)(z - 4) << 20);
    }
    long i = ((long)blockIdx.x * 256 + threadIdx.x) * 8;
    float4 a = *(const float4*)(src + i);
    float4 b = *(const float4*)(src + i + 4);
    uint32_t h0 = packbf(a.x, a.y), h1 = packbf(a.z, a.w);
    uint32_t h2 = packbf(b.x, b.y), h3 = packbf(b.z, b.w);
    uint32_t l0 = packbf_lo(a.x, a.y, h0), l1 = packbf_lo(a.z, a.w, h1);
    uint32_t l2 = packbf_lo(b.x, b.y, h2), l3 = packbf_lo(b.z, b.w, h3);
    *(uint4*)(dh + i) = make_uint4(h0, h1, h2, h3);
    *(uint4*)(dl + i) = make_uint4(l0, l1, l2, l3);
}

// ============================================================================
// bf16 cp.async GEMM: C = A W^T (+bias). BM=BN=128, BK=32, 3-stage pipeline,
// ONE barrier per chunk (wait -> sync -> issue(c+2) -> consume(c)).
// ============================================================================
__device__ __forceinline__ void gemm_issue(
    const __nv_bfloat16* __restrict__ Ah, const __nv_bfloat16* __restrict__ Al,
    const __nv_bfloat16* __restrict__ Wh, const __nv_bfloat16* __restrict__ Wl,
    int m0, int n0, int s, uint32_t sb, int tid)
{
    const int kc = s * 32;
    const uint32_t stb = sb + (uint32_t)((s % 3) * 32768);
    #pragma unroll
    for (int it = 0; it < 8; ++it) {
        int idx  = tid + it * 256;
        int bsel = idx >> 9;
        int ci   = idx & 511;
        int row  = ci >> 2, ch = ci & 3;
        const __nv_bfloat16* src =
            (bsel == 0) ? Ah + (long)(m0 + row) * 1024 + kc + ch * 8 :
            (bsel == 1) ? Al + (long)(m0 + row) * 1024 + kc + ch * 8 :
            (bsel == 2) ? Wh + (long)(n0 + row) * 1024 + kc + ch * 8 :
                          Wl + (long)(n0 + row) * 1024 + kc + ch * 8;
        uint32_t dst = stb + (uint32_t)(bsel * 8192) + (uint32_t)(row * 64)
                     + (uint32_t)(((ch ^ ((row >> 1) & 3)) << 4));
        cpa(dst, src);
    }
}

template<int MODE>
__device__ __forceinline__ void gemm_async(
    const __nv_bfloat16* __restrict__ Ah, const __nv_bfloat16* __restrict__ Al,
    const __nv_bfloat16* __restrict__ Wh, const __nv_bfloat16* __restrict__ Wl,
    const float* __restrict__ bias,
    float* __restrict__ Cf,
    __nv_bfloat16* __restrict__ Oh, __nv_bfloat16* __restrict__ Ol,
    float* __restrict__ Of,
    char* smem)
{
    const int tid = threadIdx.x;
    const int wid = tid >> 5;
    const int l   = tid & 31;
    const int m0  = blockIdx.y * 128;
    const int n0  = blockIdx.x * 128;
    const int wm  = (wid / 4) * 64;
    const int wn  = (wid % 4) * 32;

    const int aRow = (l & 15);
    const int aCk  = (l >> 4);
    const int bRow = ((l >> 4) & 1) * 8 + (l & 7);
    const int bCk  = (l >> 3) & 1;

    float acc[4][4][4];
    #pragma unroll
    for (int a = 0; a < 4; ++a)
        #pragma unroll
        for (int b = 0; b < 4; ++b)
            #pragma unroll
            for (int c = 0; c < 4; ++c) acc[a][b][c] = 0.0f;

    const uint32_t sb = smem_u32(smem);

    gemm_issue(Ah, Al, Wh, Wl, m0, n0, 0, sb, tid); CP_COMMIT();
    gemm_issue(Ah, Al, Wh, Wl, m0, n0, 1, sb, tid); CP_COMMIT();

    for (int c = 0; c < 32; ++c) {
        if (c < 31) { CP_WAIT(1); } else { CP_WAIT(0); }
        __syncthreads();
        if (c + 2 < 32) {
            gemm_issue(Ah, Al, Wh, Wl, m0, n0, c + 2, sb, tid);
            CP_COMMIT();
        }

        const uint32_t ahi = sb + (uint32_t)((c % 3) * 32768);
        const uint32_t alo = ahi + 8192;
        const uint32_t bhi = ahi + 16384;
        const uint32_t blo = ahi + 24576;

        #pragma unroll
        for (int ks = 0; ks < 2; ++ks) {
            uint32_t ah[4][4], al[4][4], bh[2][4], bl[2][4];
            #pragma unroll
            for (int mt = 0; mt < 4; ++mt) {
                int row = wm + mt * 16 + aRow;
                uint32_t off = (uint32_t)(row * 64)
                             + (uint32_t)((((2*ks + aCk) ^ ((row >> 1) & 3)) << 4));
                ldm_x4(ah[mt], ahi + off);
                ldm_x4(al[mt], alo + off);
            }
            #pragma unroll
            for (int nb = 0; nb < 2; ++nb) {
                int row = wn + nb * 16 + bRow;
                uint32_t off = (uint32_t)(row * 64)
                             + (uint32_t)((((2*ks + bCk) ^ ((row >> 1) & 3)) << 4));
                ldm_x4(bh[nb], bhi + off);
                ldm_x4(bl[nb], blo + off);
            }
            #pragma unroll
            for (int mt = 0; mt < 4; ++mt) {
                #pragma unroll
                for (int nt = 0; nt < 4; ++nt) {
                    const uint32_t* pbh = &bh[nt >> 1][(nt & 1) * 2];
                    const uint32_t* pbl = &bl[nt >> 1][(nt & 1) * 2];
                    mma16816(acc[mt][nt], ah[mt], pbh[0], pbh[1]);
                    mma16816(acc[mt][nt], ah[mt], pbl[0], pbl[1]);
                    mma16816(acc[mt][nt], al[mt], pbh[0], pbh[1]);
                }
            }
        }
    }

    #pragma unroll
    for (int mt = 0; mt < 4; ++mt) {
        #pragma unroll
        for (int nt = 0; nt < 4; ++nt) {
            int n = n0 + wn + nt * 8 + (l & 3) * 2;
            float2 bb = *(const float2*)(bias + n);
            #pragma unroll
            for (int half = 0; half < 2; ++half) {
                int m = m0 + wm + mt * 16 + (l >> 2) + half * 8;
                float2 r;
                r.x = acc[mt][nt][half*2]   + bb.x;
                r.y = acc[mt][nt][half*2+1] + bb.y;
                if (MODE == 0) {
                    *(float2*)(Cf + (long)m * 1024 + n) = r;
                } else {
                    int b2 = m >> 11, s = m & 2047;
                    int h = n >> 6, hd = n & 63;
                    long addr = ((long)(b2 * H_ + h) * S_ + s) * HD_ + hd;
                    uint32_t hv = packbf(r.x, r.y);
                    *(uint32_t*)(Oh + addr) = hv;
                    *(uint32_t*)(Ol + addr) = packbf_lo(r.x, r.y, hv);
                    if (Of) *(float2*)(Of + addr) = r;
                }
            }
        }
    }
}

__global__ void __launch_bounds__(256, 2)
gemm_qkv(const __nv_bfloat16* __restrict__ xh, const __nv_bfloat16* __restrict__ xl,
         const __nv_bfloat16* __restrict__ wh, const __nv_bfloat16* __restrict__ wl,
         const float* __restrict__ bq, const float* __restrict__ bk,
         const float* __restrict__ bv,
         __nv_bfloat16* __restrict__ qh, __nv_bfloat16* __restrict__ ql,
         __nv_bfloat16* __restrict__ kh, __nv_bfloat16* __restrict__ kl,
         __nv_bfloat16* __restrict__ vh, __nv_bfloat16* __restrict__ vl,
         float* __restrict__ vf)
{
    extern __shared__ char smem[];
    const int z = blockIdx.z;
    const __nv_bfloat16* Wh = wh + ((long)z << 20);
    const __nv_bfloat16* Wl = wl + ((long)z << 20);
    const float* bias = (z == 0) ? bq : (z == 1) ? bk : bv;
    __nv_bfloat16* Oh = (z == 0) ? qh : (z == 1) ? kh : vh;
    __nv_bfloat16* Ol = (z == 0) ? ql : (z == 1) ? kl : vl;
    float* Of = (z == 2) ? vf : nullptr;
    gemm_async<1>(xh, xl, Wh, Wl, bias, nullptr, Oh, Ol, Of, smem);
}

__global__ void __launch_bounds__(256, 2)
gemm_out(const __nv_bfloat16* __restrict__ ah, const __nv_bfloat16* __restrict__ al,
         const __nv_bfloat16* __restrict__ wh, const __nv_bfloat16* __restrict__ wl,
         const float* __restrict__ bias, float* __restrict__ C)
{
    extern __shared__ char smem[];
    gemm_async<0>(ah, al, wh + ((long)3 << 20), wl + ((long)3 << 20),
                  bias, C, nullptr, nullptr, nullptr, smem);
}

// ============================================================================
// Fused attention, 2 CTAs/SM: KV block 64 rows, 32 iterations.
// smem: Q hi/lo 32K | K 2x16K | V 2x16K = 96 KB.
// Q tile: 128 rows x 128B, swizzle ch^(row&7); K/V tiles: 64 rows x 128B.
// ============================================================================
__device__ __forceinline__ void issue_q(const __nv_bfloat16* __restrict__ Gh,
    const __nv_bfloat16* __restrict__ Gl, uint32_t dst_hi, int tid)
{
    #pragma unroll
    for (int it = 0; it < 4; ++it) {
        int idx = tid + it * 256;
        int row = idx >> 3, ch = idx & 7;
        uint32_t off = (uint32_t)(row * 128) + (uint32_t)(((ch ^ (row & 7)) << 4));
        cpa(dst_hi + off,         Gh + row * 64 + ch * 8);
        cpa(dst_hi + 16384 + off, Gl + row * 64 + ch * 8);
    }
}
__device__ __forceinline__ void issue_kv64(const __nv_bfloat16* __restrict__ Gh,
    const __nv_bfloat16* __restrict__ Gl, uint32_t dst_hi, int tid)
{
    #pragma unroll
    for (int it = 0; it < 2; ++it) {
        int idx = tid + it * 256;       // 0..511
        int row = idx >> 3, ch = idx & 7;
        uint32_t off = (uint32_t)(row * 128) + (uint32_t)(((ch ^ (row & 7)) << 4));
        cpa(dst_hi + off,        Gh + row * 64 + ch * 8);
        cpa(dst_hi + 8192 + off, Gl + row * 64 + ch * 8);
    }
}

__global__ void __launch_bounds__(256, 2)
fused_attn(const __nv_bfloat16* __restrict__ Qh, const __nv_bfloat16* __restrict__ Ql,
           const __nv_bfloat16* __restrict__ Kh, const __nv_bfloat16* __restrict__ Kl,
           const __nv_bfloat16* __restrict__ Vh, const __nv_bfloat16* __restrict__ Vl,
           const float* __restrict__ VF,
           __nv_bfloat16* __restrict__ OBh, __nv_bfloat16* __restrict__ OBl)
{
    extern __shared__ char sm[];
    const int tid = threadIdx.x;
    const int wid = tid >> 5;
    const int l   = tid & 31;
    const int g   = blockIdx.y;
    const int m0  = blockIdx.x * 128;
    const int wm  = wid * 16;

    const long gbase = (long)g * S_ * HD_;
    const __nv_bfloat16* Kgh = Kh + gbase;
    const __nv_bfloat16* Kgl = Kl + gbase;
    const __nv_bfloat16* Vgh = Vh + gbase;
    const __nv_bfloat16* Vgl = Vl + gbase;

    const uint32_t sb = smem_u32(sm);
    const uint32_t qb = sb;

    // prologue: Q + K0 + V0 as group 0
    issue_q(Qh + gbase + (long)m0 * HD_, Ql + gbase + (long)m0 * HD_, sb, tid);
    issue_kv64(Kgh, Kgl, sb + 32768, tid);
    issue_kv64(Vgh, Vgl, sb + 65536, tid);
    CP_COMMIT();

    float oacc[8][4];
    #pragma unroll
    for (int i = 0; i < 8; ++i)
        #pragma unroll
        for (int j = 0; j < 4; ++j) oacc[i][j] = 0.0f;
    float mrun[2] = {-1e30f, -1e30f};   // log2 domain
    float lsum[2] = {0.0f, 0.0f};

    const int aR = wm + (l & 15);
    const int bR = ((l >> 4) & 1) * 8 + (l & 7);
    const int bC = (l >> 3) & 1;
    const int vR = (l & 15);
    const int vC = (l >> 4);

    for (int j = 0; j < 32; ++j) {
        const int cur = j & 1;
        const uint32_t kb = sb + 32768 + cur * 16384;
        const uint32_t vb = sb + 65536 + cur * 16384;

        __syncthreads();   // buffer (j+1)&1 free (consumed in iter j-1)
        if (j + 1 < 32) {
            const int nxt = cur ^ 1;
            issue_kv64(Kgh + (long)(j + 1) * 4096, Kgl + (long)(j + 1) * 4096,
                       sb + 32768 + nxt * 16384, tid);
            issue_kv64(Vgh + (long)(j + 1) * 4096, Vgl + (long)(j + 1) * 4096,
                       sb + 65536 + nxt * 16384, tid);
            CP_COMMIT();
        }
        if (j < 31) { CP_WAIT(1); } else { CP_WAIT(0); }
        __syncthreads();

        // ---- S = Q K^T : warp tile 16 x 64 ----
        float sacc[8][4];
        #pragma unroll
        for (int i = 0; i < 8; ++i)
            #pragma unroll
            for (int c = 0; c < 4; ++c) sacc[i][c] = 0.0f;

        #pragma unroll
        for (int ks = 0; ks < 4; ++ks) {
            uint32_t ah[4], al[4];
            {
                uint32_t off = (uint32_t)(aR * 128)
                             + (uint32_t)((((ks * 2 + (l >> 4)) ^ (aR & 7)) << 4));
                ldm_x4(ah, qb + off);
                ldm_x4(al, qb + 16384 + off);
            }
            #pragma unroll
            for (int nb = 0; nb < 4; ++nb) {
                uint32_t bh[4], bl[4];
                int row = nb * 16 + bR;
                uint32_t off = (uint32_t)(row * 128)
                             + (uint32_t)((((ks * 2 + bC) ^ (row & 7)) << 4));
                ldm_x4(bh, kb + off);
                ldm_x4(bl, kb + 8192 + off);
                #pragma unroll
                for (int nt2 = 0; nt2 < 2; ++nt2) {
                    float* c = sacc[nb * 2 + nt2];
                    mma16816(c, ah, bh[nt2*2], bh[nt2*2+1]);
                    mma16816(c, ah, bl[nt2*2], bl[nt2*2+1]);
                    mma16816(c, al, bh[nt2*2], bh[nt2*2+1]);
                }
            }
        }

        // ---- online softmax (log2 domain; rows h=0 -> l>>2, h=1 -> +8) ----
        float mnew[2] = {-1e30f, -1e30f};
        #pragma unroll
        for (int nt = 0; nt < 8; ++nt) {
            #pragma unroll
            for (int c = 0; c < 4; ++c) sacc[nt][c] *= SSCALE;
            mnew[0] = fmaxf(mnew[0], fmaxf(sacc[nt][0], sacc[nt][1]));
            mnew[1] = fmaxf(mnew[1], fmaxf(sacc[nt][2], sacc[nt][3]));
        }
        #pragma unroll
        for (int h = 0; h < 2; ++h) {
            mnew[h] = fmaxf(mnew[h], __shfl_xor_sync(0xffffffffu, mnew[h], 1));
            mnew[h] = fmaxf(mnew[h], __shfl_xor_sync(0xffffffffu, mnew[h], 2));
        }
        float corr[2];
        #pragma unroll
        for (int h = 0; h < 2; ++h) {
            float mi = fmaxf(mrun[h], mnew[h]);
            corr[h] = fexp2(mrun[h] - mi);
            mrun[h] = mi;
            lsum[h] *= corr[h];
        }
        float rs[2] = {0.0f, 0.0f};
        #pragma unroll
        for (int nt = 0; nt < 8; ++nt) {
            sacc[nt][0] = fexp2(sacc[nt][0] - mrun[0]);
            sacc[nt][1] = fexp2(sacc[nt][1] - mrun[0]);
            sacc[nt][2] = fexp2(sacc[nt][2] - mrun[1]);
            sacc[nt][3] = fexp2(sacc[nt][3] - mrun[1]);
            rs[0] += sacc[nt][0] + sacc[nt][1];
            rs[1] += sacc[nt][2] + sacc[nt][3];
        }
        #pragma unroll
        for (int h = 0; h < 2; ++h) {
            rs[h] += __shfl_xor_sync(0xffffffffu, rs[h], 1);
            rs[h] += __shfl_xor_sync(0xffffffffu, rs[h], 2);
            lsum[h] += rs[h];
        }
        #pragma unroll
        for (int nt = 0; nt < 8; ++nt) {
            oacc[nt][0] *= corr[0]; oacc[nt][1] *= corr[0];
            oacc[nt][2] *= corr[1]; oacc[nt][3] *= corr[1];
        }

        // ---- O += P V ----
        #pragma unroll
        for (int kt = 0; kt < 4; ++kt) {
            uint32_t ph[4], pl[4];
            ph[0] = packbf(sacc[2*kt][0],   sacc[2*kt][1]);
            ph[1] = packbf(sacc[2*kt][2],   sacc[2*kt][3]);
            ph[2] = packbf(sacc[2*kt+1][0], sacc[2*kt+1][1]);
            ph[3] = packbf(sacc[2*kt+1][2], sacc[2*kt+1][3]);
            pl[0] = packbf_lo(sacc[2*kt][0],   sacc[2*kt][1],   ph[0]);
            pl[1] = packbf_lo(sacc[2*kt][2],   sacc[2*kt][3],   ph[1]);
            pl[2] = packbf_lo(sacc[2*kt+1][0], sacc[2*kt+1][1], ph[2]);
            pl[3] = packbf_lo(sacc[2*kt+1][2], sacc[2*kt+1][3], ph[3]);
            #pragma unroll
            for (int np = 0; np < 4; ++np) {
                uint32_t vh[4], vl[4];
                int row = kt * 16 + vR;
                uint32_t off = (uint32_t)(row * 128)
                             + (uint32_t)((((np * 2 + vC) ^ (row & 7)) << 4));
                ldm_x4_t(vh, vb + off);
                ldm_x4_t(vl, vb + 8192 + off);
                #pragma unroll
                for (int d2 = 0; d2 < 2; ++d2) {
                    float* c = oacc[np * 2 + d2];
                    mma16816(c, ph, vh[d2*2], vh[d2*2+1]);
                    mma16816(c, ph, vl[d2*2], vl[d2*2+1]);
                    mma16816(c, pl, vh[d2*2], vh[d2*2+1]);
                }
            }
        }
    }

    // ---- finalize: 1/l, Gram-Schmidt exclusion, bf16 hi/lo store [b,s,d] ----
    float inv[2] = {1.0f / lsum[0], 1.0f / lsum[1]};
    #pragma unroll
    for (int nt = 0; nt < 8; ++nt) {
        oacc[nt][0] *= inv[0]; oacc[nt][1] *= inv[0];
        oacc[nt][2] *= inv[1]; oacc[nt][3] *= inv[1];
    }

    const int bb = g >> 4, hh = g & 15;
    #pragma unroll
    for (int half = 0; half < 2; ++half) {
        int grow = m0 + wm + (l >> 2) + half * 8;
        const float* vr = VF + gbase + (long)grow * HD_;
        float vv[16];
        float dov = 0.0f, dvv = 0.0f;
        #pragma unroll
        for (int nt = 0; nt < 8; ++nt) {
            float2 t = *(const float2*)(vr + nt * 8 + (l & 3) * 2);
            vv[2*nt] = t.x; vv[2*nt+1] = t.y;
            float o0 = oacc[nt][half*2], o1 = oacc[nt][half*2+1];
            dov += o0 * t.x + o1 * t.y;
            dvv += t.x * t.x + t.y * t.y;
        }
        dov += __shfl_xor_sync(0xffffffffu, dov, 1);
        dov += __shfl_xor_sync(0xffffffffu, dov, 2);
        dvv += __shfl_xor_sync(0xffffffffu, dvv, 1);
        dvv += __shfl_xor_sync(0xffffffffu, dvv, 2);
        float al_ = dov / (dvv + 1e-8f);
        long obase = (long)(bb * S_ + grow) * D_ + hh * HD_;
        #pragma unroll
        for (int nt = 0; nt < 8; ++nt) {
            float rx = oacc[nt][half*2]   - al_ * vv[2*nt];
            float ry = oacc[nt][half*2+1] - al_ * vv[2*nt+1];
            long a = obase + nt * 8 + (l & 3) * 2;
            uint32_t hv = packbf(rx, ry);
            *(uint32_t*)(OBh + a) = hv;
            *(uint32_t*)(OBl + a) = packbf_lo(rx, ry, hv);
        }
    }
}

// ============================================================================
extern "C" void kernel_launch(void* const* d_in, const int* in_sizes, int n_in,
                              void* d_out, int out_size)
{
    const float* x  = (const float*)d_in[0];
    const float* wq = (const float*)d_in[1];
    const float* bq = (const float*)d_in[2];
    const float* wk = (const float*)d_in[3];
    const float* bk = (const float*)d_in[4];
    const float* wv = (const float*)d_in[5];
    const float* bv = (const float*)d_in[6];
    const float* wo = (const float*)d_in[7];
    const float* bo = (const float*)d_in[8];
    float* out = (float*)d_out;

    __nv_bfloat16 *xh, *xl, *wh, *wl, *qh, *ql, *kh, *kl, *vh, *vl, *obh, *obl;
    float *vf;
    cudaGetSymbolAddress((void**)&xh,  g_xh);
    cudaGetSymbolAddress((void**)&xl,  g_xl);
    cudaGetSymbolAddress((void**)&wh,  g_wh);
    cudaGetSymbolAddress((void**)&wl,  g_wl);
    cudaGetSymbolAddress((void**)&qh,  g_qh);
    cudaGetSymbolAddress((void**)&ql,  g_ql);
    cudaGetSymbolAddress((void**)&kh,  g_kh);
    cudaGetSymbolAddress((void**)&kl,  g_kl);
    cudaGetSymbolAddress((void**)&vh,  g_vh);
    cudaGetSymbolAddress((void**)&vl,  g_vl);
    cudaGetSymbolAddress((void**)&vf,  g_vf);
    cudaGetSymbolAddress((void**)&obh, g_obh);
    cudaGetSymbolAddress((void**)&obl, g_obl);

    const int SMG = 3 * 32768;     // 98304
    const int SMF = 98304;         // Q 32K + K 32K + V 32K
    cudaFuncSetAttribute(gemm_qkv,  cudaFuncAttributeMaxDynamicSharedMemorySize, SMG);
    cudaFuncSetAttribute(gemm_out,  cudaFuncAttributeMaxDynamicSharedMemorySize, SMG);
    cudaFuncSetAttribute(fused_attn, cudaFuncAttributeMaxDynamicSharedMemorySize, SMF);

    // 0) convert x + weights to bf16 hi/lo
    convert_all<<<dim3(512, 8), 256>>>(x, wq, wk, wv, wo, xh, xl, wh, wl);

    // 1) Q/K/V projections -> bf16 hi/lo head layout (+ V fp32)
    gemm_qkv<<<dim3(D_/128, M_/128, 3), 256, SMG>>>(
        xh, xl, wh, wl, bq, bk, bv, qh, ql, kh, kl, vh, vl, vf);

    // 2) fused attention + softmax + exclusion -> ob bf16 hi/lo [b,s,d]
    fused_attn<<<dim3(S_/128, G_), 256, SMF>>>(
        qh, ql, kh, kl, vh, vl, vf, obh, obl);

    // 3) output projection -> d_out
    gemm_out<<<dim3(D_/128, M_/128, 1), 256, SMG>>>(obh, obl, wh, wl, bo, out);
}